// round 6
// baseline (speedup 1.0000x reference)
#include <cuda_runtime.h>
#include <math.h>
#include <cstdint>

#define Bb 4
#define Nn 2048
#define Dd 768
#define Hh 12
#define DH 64
#define M_TOT (Bb*Nn)      /* 8192 */
#define BH (Bb*Hh)         /* 48   */

// ---------------- scratch (device globals; no allocs allowed) ----------------
__device__ float g_xn  [(size_t)M_TOT * Dd];
__device__ float g_qkv [(size_t)M_TOT * 3 * Dd];
__device__ float g_q   [(size_t)BH * Nn * DH];
__device__ float g_k   [(size_t)BH * Nn * DH];
__device__ float g_v   [(size_t)BH * Nn * DH];
__device__ float g_ao  [(size_t)M_TOT * Dd];
__device__ float g_wq  [(size_t)3 * Dd * Dd];   // tf32-rounded w_qkv
__device__ float g_wo  [(size_t)Dd * Dd];       // tf32-rounded w_out

// ======================= helpers =======================
__device__ __forceinline__ uint32_t smem_u32(const void* p) {
    uint32_t a;
    asm("{ .reg .u64 t; cvta.to.shared.u64 t, %1; cvt.u32.u64 %0, t; }" : "=r"(a) : "l"(p));
    return a;
}
__device__ __forceinline__ void cp16(uint32_t dst, const void* src) {
    asm volatile("cp.async.cg.shared.global [%0], [%1], 16;" :: "r"(dst), "l"(src) : "memory");
}
__device__ __forceinline__ uint32_t cvt_tf32(float x) {
    uint32_t r;
    asm("cvt.rna.tf32.f32 %0, %1;" : "=r"(r) : "f"(x));
    return r;
}
__device__ __forceinline__ float rnd_tf32(float x) {
    return __uint_as_float(cvt_tf32(x));
}
__device__ __forceinline__ void mma_tf32(float* c, uint32_t a0, uint32_t a1, uint32_t a2, uint32_t a3,
                                         uint32_t b0, uint32_t b1) {
    asm volatile("mma.sync.aligned.m16n8k8.row.col.f32.tf32.tf32.f32 "
                 "{%0,%1,%2,%3}, {%4,%5,%6,%7}, {%8,%9}, {%0,%1,%2,%3};"
                 : "+f"(c[0]), "+f"(c[1]), "+f"(c[2]), "+f"(c[3])
                 : "r"(a0), "r"(a1), "r"(a2), "r"(a3), "r"(b0), "r"(b1));
}

// ---------------- tf32 rounding pass (weights) ----------------
__global__ __launch_bounds__(256) void cvtw_kernel(const float* __restrict__ src,
                                                   float* __restrict__ dst, int n)
{
    const int i = (blockIdx.x * 256 + threadIdx.x) * 4;
    if (i < n) {
        float4 v = *(const float4*)&src[i];
        v.x = rnd_tf32(v.x); v.y = rnd_tf32(v.y);
        v.z = rnd_tf32(v.z); v.w = rnd_tf32(v.w);
        *(float4*)&dst[i] = v;
    }
}

// ---------------- LayerNorm (writes tf32-rounded) ----------------
__global__ __launch_bounds__(256) void ln_kernel(const float* __restrict__ x,
                                                 const float* __restrict__ gamma,
                                                 const float* __restrict__ beta,
                                                 float* __restrict__ xn)
{
    const int row = blockIdx.x;
    const int t   = threadIdx.x;
    const float* xr = x + (size_t)row * Dd;
    float v0 = xr[t], v1 = xr[t + 256], v2 = xr[t + 512];
    float s  = v0 + v1 + v2;
    float sq = v0*v0 + v1*v1 + v2*v2;
    #pragma unroll
    for (int off = 16; off; off >>= 1) {
        s  += __shfl_xor_sync(0xffffffffu, s,  off);
        sq += __shfl_xor_sync(0xffffffffu, sq, off);
    }
    __shared__ float rs[8], rq[8];
    const int w = t >> 5, lane = t & 31;
    if (lane == 0) { rs[w] = s; rq[w] = sq; }
    __syncthreads();
    if (t == 0) {
        float S = 0.f, Q = 0.f;
        #pragma unroll
        for (int i = 0; i < 8; i++) { S += rs[i]; Q += rq[i]; }
        rs[0] = S; rq[0] = Q;
    }
    __syncthreads();
    const float mu   = rs[0] * (1.0f / 768.0f);
    const float var  = rq[0] * (1.0f / 768.0f) - mu * mu;
    const float rstd = rsqrtf(var + 1e-5f);
    float* xo = xn + (size_t)row * Dd;
    xo[t      ] = rnd_tf32((v0 - mu) * rstd * gamma[t      ] + beta[t      ]);
    xo[t + 256] = rnd_tf32((v1 - mu) * rstd * gamma[t + 256] + beta[t + 256]);
    xo[t + 512] = rnd_tf32((v2 - mu) * rstd * gamma[t + 512] + beta[t + 512]);
}

// ---------------- mma.sync tf32 GEMM (pre-rounded operands; 2 CTA/SM) ----------------
#define ASTR 36
#define TILE_F (128 * ASTR)
__global__ __launch_bounds__(256, 2) void gemm_mma(const float* __restrict__ A,
                                                   const float* __restrict__ W,
                                                   float* __restrict__ C,
                                                   int Np, int K)
{
    extern __shared__ __align__(16) float sg[];
    const int tid  = threadIdx.x;
    const int lane = tid & 31;
    const int wid  = tid >> 5;
    const int wm   = wid >> 2;
    const int wn   = wid & 3;
    const int gq   = lane >> 2;
    const int jq   = lane & 3;
    const int bm   = blockIdx.y * 128;
    const int bn   = blockIdx.x * 128;

    float acc[4][4][4];
    #pragma unroll
    for (int i = 0; i < 4; i++)
        #pragma unroll
        for (int j = 0; j < 4; j++)
            #pragma unroll
            for (int q = 0; q < 4; q++) acc[i][j][q] = 0.f;

    const int nCh = K / 32;

#define LOAD_STAGE(IT, S) do {                                                \
    const float* Ab = A + (size_t)bm * K + (IT) * 32;                         \
    const float* Wb = W + (size_t)bn * K + (IT) * 32;                         \
    float* As_ = sg + (S) * (2 * TILE_F);                                     \
    float* Bs_ = As_ + TILE_F;                                                \
    _Pragma("unroll")                                                         \
    for (int p = 0; p < 4; p++) {                                             \
        const int idx = tid + p * 256;                                        \
        const int row = idx >> 3;                                             \
        const int c4  = (idx & 7) * 4;                                        \
        cp16(smem_u32(&As_[row * ASTR + c4]), &Ab[(size_t)row * K + c4]);     \
        cp16(smem_u32(&Bs_[row * ASTR + c4]), &Wb[(size_t)row * K + c4]);     \
    }                                                                         \
    asm volatile("cp.async.commit_group;" ::: "memory");                      \
} while (0)

    LOAD_STAGE(0, 0);

    for (int it = 0; it < nCh; it++) {
        const int s = it & 1;
        if (it + 1 < nCh) {
            LOAD_STAGE(it + 1, s ^ 1);
            asm volatile("cp.async.wait_group 1;" ::: "memory");
        } else {
            asm volatile("cp.async.wait_group 0;" ::: "memory");
        }
        __syncthreads();

        const float* As_ = sg + s * (2 * TILE_F);
        const float* Bs_ = As_ + TILE_F;

        #pragma unroll
        for (int half = 0; half < 2; half++) {
            uint4 bfr[4];
            #pragma unroll
            for (int nf = 0; nf < 4; nf++) {
                const int n = wn * 32 + nf * 8 + gq;
                bfr[nf] = *(const uint4*)&Bs_[n * ASTR + jq * 8 + half * 4];
            }
            #pragma unroll
            for (int mf = 0; mf < 4; mf++) {
                const int m = wm * 64 + mf * 16 + gq;
                uint4 a0 = *(const uint4*)&As_[m * ASTR + jq * 8 + half * 4];
                uint4 a1 = *(const uint4*)&As_[(m + 8) * ASTR + jq * 8 + half * 4];
                #pragma unroll
                for (int nf = 0; nf < 4; nf++) {
                    mma_tf32(acc[mf][nf], a0.x, a1.x, a0.y, a1.y, bfr[nf].x, bfr[nf].y);
                    mma_tf32(acc[mf][nf], a0.z, a1.z, a0.w, a1.w, bfr[nf].z, bfr[nf].w);
                }
            }
        }
        __syncthreads();
    }

    #pragma unroll
    for (int mf = 0; mf < 4; mf++) {
        const int r = bm + wm * 64 + mf * 16 + gq;
        #pragma unroll
        for (int nf = 0; nf < 4; nf++) {
            const int n0 = bn + wn * 32 + nf * 8 + 2 * jq;
            *(float2*)&C[(size_t)r * Np + n0]       = make_float2(acc[mf][nf][0], acc[mf][nf][1]);
            *(float2*)&C[(size_t)(r + 8) * Np + n0] = make_float2(acc[mf][nf][2], acc[mf][nf][3]);
        }
    }
#undef LOAD_STAGE
}

// ---------------- RoPE + head split (writes tf32-rounded Q/K/V) ----------------
__global__ __launch_bounds__(256) void rope_kernel(const float* __restrict__ qkv,
                                                   const float* __restrict__ coords,
                                                   float* __restrict__ Qo,
                                                   float* __restrict__ Ko,
                                                   float* __restrict__ Vo)
{
    const int m = blockIdx.x;
    const int b = m >> 11;
    const int n = m & 2047;
    const float c0 = coords[m * 2 + 0];
    const float c1 = coords[m * 2 + 1];
    const float* src = qkv + (size_t)m * (3 * Dd);

    for (int t = threadIdx.x; t < 3 * Dd; t += 256) {
        const int which = t / Dd;
        const int r     = t - which * Dd;
        const int h     = r >> 6;
        const int d     = r & 63;
        float val;
        if (which == 2) {
            val = src[t];
        } else {
            const int slice = d >> 5;
            const int dl    = d & 31;
            const int j     = dl & 15;
            const int isodd = dl >> 4;
            const float coord = slice ? c1 : c0;
            const float invf  = exp2f(-13.0f * (float)j * (1.0f / 16.0f));
            const float f  = coord * invf;
            const float cs = cosf(f);
            const float sn = sinf(f);
            const int   e  = which * Dd + h * 64 + slice * 32 + 2 * j;
            const float t1 = src[e];
            const float t2 = src[e + 1];
            val = isodd ? (t1 * sn + t2 * cs) : (t1 * cs - t2 * sn);
            if (which == 0) val *= 0.125f;
        }
        float* dst = (which == 0) ? Qo : ((which == 1) ? Ko : Vo);
        dst[((size_t)(b * Hh + h) * Nn + n) * DH + d] = rnd_tf32(val);
    }
}

// ---------------- mma.sync tf32 flash attention (Bq=128, 2 CTA/SM) ----------------
// 8 warps, warp w owns q-rows [16w,16w+16). smem tiles hold tf32 bits; only P cvts.
#define FSTR 68
__global__ __launch_bounds__(256, 2) void attn_mma(const float* __restrict__ Q,
                                                   const float* __restrict__ K,
                                                   const float* __restrict__ V,
                                                   float* __restrict__ AO)
{
    extern __shared__ __align__(16) uint32_t sa[];
    uint32_t* Qs = sa;                     // [128][FSTR]
    uint32_t* Ps = Qs + 128 * FSTR;        // [128][FSTR]
    uint32_t* Ks = Ps + 128 * FSTR;        // [64][FSTR]
    uint32_t* Vt = Ks + 64 * FSTR;         // [64][FSTR]  (d-major)

    const int tid  = threadIdx.x;
    const int lane = tid & 31;
    const int wid  = tid >> 5;
    const int gq   = lane >> 2;
    const int jq   = lane & 3;
    const int m0   = wid * 16;
    const int bh   = blockIdx.y;
    const int q0   = blockIdx.x * 128;
    const int b    = bh / Hh;
    const int h    = bh - b * Hh;

    const float* Qbh = Q + (size_t)bh * Nn * DH;
    const float* Kbh = K + (size_t)bh * Nn * DH;
    const float* Vbh = V + (size_t)bh * Nn * DH;

    // stage Q tile (128x64), raw copy (pre-rounded)
    #pragma unroll
    for (int p = 0; p < 8; p++) {
        const int idx = tid + p * 256;     // 0..2047
        const int row = idx >> 4;
        const int c4  = (idx & 15) * 4;
        *(uint4*)&Qs[row * FSTR + c4] = *(const uint4*)&Qbh[(size_t)(q0 + row) * DH + c4];
    }

    float o[8][4];
    #pragma unroll
    for (int t = 0; t < 8; t++)
        #pragma unroll
        for (int j = 0; j < 4; j++) o[t][j] = 0.f;
    float m_lo = -1e30f, m_hi = -1e30f, l_lo = 0.f, l_hi = 0.f;

    for (int k0 = 0; k0 < Nn; k0 += 64) {
        __syncthreads();
        // stage K tile (64x64) raw
        #pragma unroll
        for (int p = 0; p < 4; p++) {
            const int idx = tid + p * 256;
            const int row = idx >> 4;
            const int c4  = (idx & 15) * 4;
            *(uint4*)&Ks[row * FSTR + c4] = *(const uint4*)&Kbh[(size_t)(k0 + row) * DH + c4];
        }
        // stage V transposed: Vt[d][k] raw
        #pragma unroll
        for (int p = 0; p < 4; p++) {
            const int idx = tid + p * 256;
            const int kk  = idx & 63;
            const int d0  = (idx >> 6) * 4;
            uint4 vv = *(const uint4*)&Vbh[(size_t)(k0 + kk) * DH + d0];
            Vt[(d0 + 0) * FSTR + kk] = vv.x;
            Vt[(d0 + 1) * FSTR + kk] = vv.y;
            Vt[(d0 + 2) * FSTR + kk] = vv.z;
            Vt[(d0 + 3) * FSTR + kk] = vv.w;
        }
        __syncthreads();

        // ---- S = Q K^T ----
        float s[8][4];
        #pragma unroll
        for (int t = 0; t < 8; t++)
            #pragma unroll
            for (int j = 0; j < 4; j++) s[t][j] = 0.f;

        #pragma unroll
        for (int g = 0; g < 2; g++) {
            #pragma unroll
            for (int half = 0; half < 2; half++) {
                const int kc = g * 32 + half * 4 + jq * 8;
                uint4 a0 = *(const uint4*)&Qs[(m0 + gq) * FSTR + kc];
                uint4 a1 = *(const uint4*)&Qs[(m0 + gq + 8) * FSTR + kc];
                #pragma unroll
                for (int t = 0; t < 8; t++) {
                    uint4 bv = *(const uint4*)&Ks[(t * 8 + gq) * FSTR + kc];
                    mma_tf32(s[t], a0.x, a1.x, a0.y, a1.y, bv.x, bv.y);
                    mma_tf32(s[t], a0.z, a1.z, a0.w, a1.w, bv.z, bv.w);
                }
            }
        }

        // ---- online softmax (rows gq -> c0,c1 ; gq+8 -> c2,c3) ----
        float smax_lo = -1e30f, smax_hi = -1e30f;
        #pragma unroll
        for (int t = 0; t < 8; t++) {
            smax_lo = fmaxf(smax_lo, fmaxf(s[t][0], s[t][1]));
            smax_hi = fmaxf(smax_hi, fmaxf(s[t][2], s[t][3]));
        }
        #pragma unroll
        for (int off = 1; off <= 2; off <<= 1) {
            smax_lo = fmaxf(smax_lo, __shfl_xor_sync(0xffffffffu, smax_lo, off));
            smax_hi = fmaxf(smax_hi, __shfl_xor_sync(0xffffffffu, smax_hi, off));
        }
        const float mn_lo = fmaxf(m_lo, smax_lo);
        const float mn_hi = fmaxf(m_hi, smax_hi);
        const float cr_lo = __expf(m_lo - mn_lo);
        const float cr_hi = __expf(m_hi - mn_hi);
        m_lo = mn_lo; m_hi = mn_hi;

        float ls_lo = 0.f, ls_hi = 0.f;
        #pragma unroll
        for (int t = 0; t < 8; t++) {
            float p0 = __expf(s[t][0] - mn_lo);
            float p1 = __expf(s[t][1] - mn_lo);
            float p2 = __expf(s[t][2] - mn_hi);
            float p3 = __expf(s[t][3] - mn_hi);
            ls_lo += p0 + p1;  ls_hi += p2 + p3;
            const int col = t * 8 + 2 * jq;
            Ps[(m0 + gq) * FSTR + col]         = cvt_tf32(p0);
            Ps[(m0 + gq) * FSTR + col + 1]     = cvt_tf32(p1);
            Ps[(m0 + gq + 8) * FSTR + col]     = cvt_tf32(p2);
            Ps[(m0 + gq + 8) * FSTR + col + 1] = cvt_tf32(p3);
        }
        #pragma unroll
        for (int off = 1; off <= 2; off <<= 1) {
            ls_lo += __shfl_xor_sync(0xffffffffu, ls_lo, off);
            ls_hi += __shfl_xor_sync(0xffffffffu, ls_hi, off);
        }
        l_lo = l_lo * cr_lo + ls_lo;
        l_hi = l_hi * cr_hi + ls_hi;
        #pragma unroll
        for (int t = 0; t < 8; t++) {
            o[t][0] *= cr_lo; o[t][1] *= cr_lo;
            o[t][2] *= cr_hi; o[t][3] *= cr_hi;
        }
        __syncwarp();

        // ---- O += P V ----
        #pragma unroll
        for (int g = 0; g < 2; g++) {
            #pragma unroll
            for (int half = 0; half < 2; half++) {
                const int kc = g * 32 + half * 4 + jq * 8;
                uint4 a0 = *(const uint4*)&Ps[(m0 + gq) * FSTR + kc];
                uint4 a1 = *(const uint4*)&Ps[(m0 + gq + 8) * FSTR + kc];
                #pragma unroll
                for (int t = 0; t < 8; t++) {
                    uint4 bv = *(const uint4*)&Vt[(t * 8 + gq) * FSTR + kc];
                    mma_tf32(o[t], a0.x, a1.x, a0.y, a1.y, bv.x, bv.y);
                    mma_tf32(o[t], a0.z, a1.z, a0.w, a1.w, bv.z, bv.w);
                }
            }
        }
    }

    // epilogue: normalize, round to tf32, write AO[b][n][h*64+d]
    const float inv_lo = 1.0f / l_lo;
    const float inv_hi = 1.0f / l_hi;
    #pragma unroll
    for (int t = 0; t < 8; t++) {
        const int col = h * DH + t * 8 + 2 * jq;
        const size_t r0 = (size_t)(b * Nn + q0 + m0 + gq) * Dd + col;
        const size_t r1 = (size_t)(b * Nn + q0 + m0 + gq + 8) * Dd + col;
        *(float2*)&AO[r0] = make_float2(rnd_tf32(o[t][0] * inv_lo), rnd_tf32(o[t][1] * inv_lo));
        *(float2*)&AO[r1] = make_float2(rnd_tf32(o[t][2] * inv_hi), rnd_tf32(o[t][3] * inv_hi));
    }
}

// ---------------- launch ----------------
extern "C" void kernel_launch(void* const* d_in, const int* in_sizes, int n_in,
                              void* d_out, int out_size)
{
    const float* x      = (const float*)d_in[0];
    const float* coords = (const float*)d_in[1];
    const float* gamma  = (const float*)d_in[2];
    const float* beta   = (const float*)d_in[3];
    const float* wqkv   = (const float*)d_in[4];
    const float* wout   = (const float*)d_in[5];
    float* out = (float*)d_out;

    float *xn, *qkv, *q, *k, *v, *ao, *wq, *wo;
    cudaGetSymbolAddress((void**)&xn,  g_xn);
    cudaGetSymbolAddress((void**)&qkv, g_qkv);
    cudaGetSymbolAddress((void**)&q,   g_q);
    cudaGetSymbolAddress((void**)&k,   g_k);
    cudaGetSymbolAddress((void**)&v,   g_v);
    cudaGetSymbolAddress((void**)&ao,  g_ao);
    cudaGetSymbolAddress((void**)&wq,  g_wq);
    cudaGetSymbolAddress((void**)&wo,  g_wo);

    const int gemm_smem = 2 * 2 * TILE_F * (int)sizeof(float);          // 73728 B
    const int attn_smem = (2 * 128 * FSTR + 2 * 64 * FSTR) * 4;         // 104448 B
    cudaFuncSetAttribute(gemm_mma, cudaFuncAttributeMaxDynamicSharedMemorySize, gemm_smem);
    cudaFuncSetAttribute(attn_mma, cudaFuncAttributeMaxDynamicSharedMemorySize, attn_smem);

    const int nwq = 3 * Dd * Dd, nwo = Dd * Dd;
    cvtw_kernel<<<nwq / 1024, 256>>>(wqkv, wq, nwq);
    cvtw_kernel<<<nwo / 1024, 256>>>(wout, wo, nwo);
    ln_kernel<<<M_TOT, 256>>>(x, gamma, beta, xn);
    gemm_mma<<<dim3(3 * Dd / 128, M_TOT / 128), 256, gemm_smem>>>(xn, wq, qkv, 3 * Dd, Dd);
    rope_kernel<<<M_TOT, 256>>>(qkv, coords, q, k, v);
    attn_mma<<<dim3(Nn / 128, BH), 256, attn_smem>>>(q, k, v, ao);
    gemm_mma<<<dim3(Dd / 128, M_TOT / 128), 256, gemm_smem>>>(ao, wo, out, Dd, Dd);
}

// round 7
// speedup vs baseline: 1.0613x; 1.0613x over previous
#include <cuda_runtime.h>
#include <math.h>
#include <cstdint>

#define Bb 4
#define Nn 2048
#define Dd 768
#define Hh 12
#define DH 64
#define M_TOT (Bb*Nn)      /* 8192 */
#define BH (Bb*Hh)         /* 48   */

// ---------------- scratch (device globals; no allocs allowed) ----------------
__device__ float g_xn  [(size_t)M_TOT * Dd];
__device__ float g_qkv [(size_t)M_TOT * 3 * Dd];
__device__ float g_q   [(size_t)BH * Nn * DH];
__device__ float g_k   [(size_t)BH * Nn * DH];
__device__ float g_v   [(size_t)BH * Nn * DH];
__device__ float g_ao  [(size_t)M_TOT * Dd];
__device__ float g_wq  [(size_t)3 * Dd * Dd];   // tf32-rounded w_qkv
__device__ float g_wo  [(size_t)Dd * Dd];       // tf32-rounded w_out

// ======================= helpers =======================
__device__ __forceinline__ uint32_t smem_u32(const void* p) {
    uint32_t a;
    asm("{ .reg .u64 t; cvta.to.shared.u64 t, %1; cvt.u32.u64 %0, t; }" : "=r"(a) : "l"(p));
    return a;
}
__device__ __forceinline__ void cp16(uint32_t dst, const void* src) {
    asm volatile("cp.async.cg.shared.global [%0], [%1], 16;" :: "r"(dst), "l"(src) : "memory");
}
__device__ __forceinline__ uint32_t cvt_tf32(float x) {
    uint32_t r;
    asm("cvt.rna.tf32.f32 %0, %1;" : "=r"(r) : "f"(x));
    return r;
}
__device__ __forceinline__ float rnd_tf32(float x) {
    return __uint_as_float(cvt_tf32(x));
}
__device__ __forceinline__ void mma_tf32(float* c, uint32_t a0, uint32_t a1, uint32_t a2, uint32_t a3,
                                         uint32_t b0, uint32_t b1) {
    asm volatile("mma.sync.aligned.m16n8k8.row.col.f32.tf32.tf32.f32 "
                 "{%0,%1,%2,%3}, {%4,%5,%6,%7}, {%8,%9}, {%0,%1,%2,%3};"
                 : "+f"(c[0]), "+f"(c[1]), "+f"(c[2]), "+f"(c[3])
                 : "r"(a0), "r"(a1), "r"(a2), "r"(a3), "r"(b0), "r"(b1));
}

// ---------------- tf32 rounding pass (weights) ----------------
__global__ __launch_bounds__(256) void cvtw_kernel(const float* __restrict__ src,
                                                   float* __restrict__ dst, int n)
{
    const int i = (blockIdx.x * 256 + threadIdx.x) * 4;
    if (i < n) {
        float4 v = *(const float4*)&src[i];
        v.x = rnd_tf32(v.x); v.y = rnd_tf32(v.y);
        v.z = rnd_tf32(v.z); v.w = rnd_tf32(v.w);
        *(float4*)&dst[i] = v;
    }
}

// ---------------- LayerNorm (writes tf32-rounded) ----------------
__global__ __launch_bounds__(256) void ln_kernel(const float* __restrict__ x,
                                                 const float* __restrict__ gamma,
                                                 const float* __restrict__ beta,
                                                 float* __restrict__ xn)
{
    const int row = blockIdx.x;
    const int t   = threadIdx.x;
    const float* xr = x + (size_t)row * Dd;
    float v0 = xr[t], v1 = xr[t + 256], v2 = xr[t + 512];
    float s  = v0 + v1 + v2;
    float sq = v0*v0 + v1*v1 + v2*v2;
    #pragma unroll
    for (int off = 16; off; off >>= 1) {
        s  += __shfl_xor_sync(0xffffffffu, s,  off);
        sq += __shfl_xor_sync(0xffffffffu, sq, off);
    }
    __shared__ float rs[8], rq[8];
    const int w = t >> 5, lane = t & 31;
    if (lane == 0) { rs[w] = s; rq[w] = sq; }
    __syncthreads();
    if (t == 0) {
        float S = 0.f, Q = 0.f;
        #pragma unroll
        for (int i = 0; i < 8; i++) { S += rs[i]; Q += rq[i]; }
        rs[0] = S; rq[0] = Q;
    }
    __syncthreads();
    const float mu   = rs[0] * (1.0f / 768.0f);
    const float var  = rq[0] * (1.0f / 768.0f) - mu * mu;
    const float rstd = rsqrtf(var + 1e-5f);
    float* xo = xn + (size_t)row * Dd;
    xo[t      ] = rnd_tf32((v0 - mu) * rstd * gamma[t      ] + beta[t      ]);
    xo[t + 256] = rnd_tf32((v1 - mu) * rstd * gamma[t + 256] + beta[t + 256]);
    xo[t + 512] = rnd_tf32((v2 - mu) * rstd * gamma[t + 512] + beta[t + 512]);
}

// ---------------- mma.sync tf32 GEMM: 4 warps, 64x64 warp tiles ----------------
#define ASTR 36
#define TILE_F (128 * ASTR)
__global__ __launch_bounds__(128, 2) void gemm_mma(const float* __restrict__ A,
                                                   const float* __restrict__ W,
                                                   float* __restrict__ C,
                                                   int Np, int K)
{
    extern __shared__ __align__(16) float sg[];
    const int tid  = threadIdx.x;
    const int lane = tid & 31;
    const int wid  = tid >> 5;          // 0..3
    const int wm   = wid >> 1;          // 0..1
    const int wn   = wid & 1;           // 0..1
    const int gq   = lane >> 2;
    const int jq   = lane & 3;
    const int bm   = blockIdx.y * 128;
    const int bn   = blockIdx.x * 128;

    float acc[4][8][4];
    #pragma unroll
    for (int i = 0; i < 4; i++)
        #pragma unroll
        for (int j = 0; j < 8; j++)
            #pragma unroll
            for (int q = 0; q < 4; q++) acc[i][j][q] = 0.f;

    const int nCh = K / 32;

#define LOAD_STAGE(IT, S) do {                                                \
    const float* Ab = A + (size_t)bm * K + (IT) * 32;                         \
    const float* Wb = W + (size_t)bn * K + (IT) * 32;                         \
    float* As_ = sg + (S) * (2 * TILE_F);                                     \
    float* Bs_ = As_ + TILE_F;                                                \
    _Pragma("unroll")                                                         \
    for (int p = 0; p < 8; p++) {                                             \
        const int idx = tid + p * 128;                                        \
        const int row = idx >> 3;                                             \
        const int c4  = (idx & 7) * 4;                                        \
        cp16(smem_u32(&As_[row * ASTR + c4]), &Ab[(size_t)row * K + c4]);     \
        cp16(smem_u32(&Bs_[row * ASTR + c4]), &Wb[(size_t)row * K + c4]);     \
    }                                                                         \
    asm volatile("cp.async.commit_group;" ::: "memory");                      \
} while (0)

    LOAD_STAGE(0, 0);

    for (int it = 0; it < nCh; it++) {
        const int s = it & 1;
        if (it + 1 < nCh) {
            LOAD_STAGE(it + 1, s ^ 1);
            asm volatile("cp.async.wait_group 1;" ::: "memory");
        } else {
            asm volatile("cp.async.wait_group 0;" ::: "memory");
        }
        __syncthreads();

        const float* As_ = sg + s * (2 * TILE_F);
        const float* Bs_ = As_ + TILE_F;

        #pragma unroll
        for (int half = 0; half < 2; half++) {
            const int kc = jq * 8 + half * 4;
            uint4 afr[8];
            #pragma unroll
            for (int mf = 0; mf < 4; mf++) {
                const int m = wm * 64 + mf * 16 + gq;
                afr[2 * mf]     = *(const uint4*)&As_[m * ASTR + kc];
                afr[2 * mf + 1] = *(const uint4*)&As_[(m + 8) * ASTR + kc];
            }
            #pragma unroll
            for (int ng = 0; ng < 2; ng++) {
                uint4 bfr[4];
                #pragma unroll
                for (int j = 0; j < 4; j++) {
                    const int n = wn * 64 + (ng * 4 + j) * 8 + gq;
                    bfr[j] = *(const uint4*)&Bs_[n * ASTR + kc];
                }
                #pragma unroll
                for (int mf = 0; mf < 4; mf++) {
                    #pragma unroll
                    for (int j = 0; j < 4; j++) {
                        float* a = acc[mf][ng * 4 + j];
                        mma_tf32(a, afr[2*mf].x, afr[2*mf+1].x, afr[2*mf].y, afr[2*mf+1].y,
                                 bfr[j].x, bfr[j].y);
                        mma_tf32(a, afr[2*mf].z, afr[2*mf+1].z, afr[2*mf].w, afr[2*mf+1].w,
                                 bfr[j].z, bfr[j].w);
                    }
                }
            }
        }
        __syncthreads();
    }

    #pragma unroll
    for (int mf = 0; mf < 4; mf++) {
        const int r = bm + wm * 64 + mf * 16 + gq;
        #pragma unroll
        for (int nf = 0; nf < 8; nf++) {
            const int n0 = bn + wn * 64 + nf * 8 + 2 * jq;
            *(float2*)&C[(size_t)r * Np + n0]       = make_float2(acc[mf][nf][0], acc[mf][nf][1]);
            *(float2*)&C[(size_t)(r + 8) * Np + n0] = make_float2(acc[mf][nf][2], acc[mf][nf][3]);
        }
    }
#undef LOAD_STAGE
}

// ---------------- RoPE + head split (writes tf32-rounded Q/K/V) ----------------
__global__ __launch_bounds__(256) void rope_kernel(const float* __restrict__ qkv,
                                                   const float* __restrict__ coords,
                                                   float* __restrict__ Qo,
                                                   float* __restrict__ Ko,
                                                   float* __restrict__ Vo)
{
    const int m = blockIdx.x;
    const int b = m >> 11;
    const int n = m & 2047;
    const float c0 = coords[m * 2 + 0];
    const float c1 = coords[m * 2 + 1];
    const float* src = qkv + (size_t)m * (3 * Dd);

    for (int t = threadIdx.x; t < 3 * Dd; t += 256) {
        const int which = t / Dd;
        const int r     = t - which * Dd;
        const int h     = r >> 6;
        const int d     = r & 63;
        float val;
        if (which == 2) {
            val = src[t];
        } else {
            const int slice = d >> 5;
            const int dl    = d & 31;
            const int j     = dl & 15;
            const int isodd = dl >> 4;
            const float coord = slice ? c1 : c0;
            const float invf  = exp2f(-13.0f * (float)j * (1.0f / 16.0f));
            const float f  = coord * invf;
            const float cs = cosf(f);
            const float sn = sinf(f);
            const int   e  = which * Dd + h * 64 + slice * 32 + 2 * j;
            const float t1 = src[e];
            const float t2 = src[e + 1];
            val = isodd ? (t1 * sn + t2 * cs) : (t1 * cs - t2 * sn);
            if (which == 0) val *= 0.125f;
        }
        float* dst = (which == 0) ? Qo : ((which == 1) ? Ko : Vo);
        dst[((size_t)(b * Hh + h) * Nn + n) * DH + d] = rnd_tf32(val);
    }
}

// ---------------- mma.sync tf32 flash attention ----------------
// Bq=128, Bk=64, 128 threads (4 warps). Warp w owns 32 q-rows (m-blocks w*32, w*32+16);
// K/Vt B-fragments loaded once and applied to both m-blocks. 2 CTAs/SM.
#define FSTR 68
__global__ __launch_bounds__(128, 2) void attn_mma(const float* __restrict__ Q,
                                                   const float* __restrict__ K,
                                                   const float* __restrict__ V,
                                                   float* __restrict__ AO)
{
    extern __shared__ __align__(16) uint32_t sa[];
    uint32_t* Qs = sa;                     // [128][FSTR]
    uint32_t* Ps = Qs + 128 * FSTR;        // [128][FSTR]
    uint32_t* Ks = Ps + 128 * FSTR;        // [64][FSTR]
    uint32_t* Vt = Ks + 64 * FSTR;         // [64][FSTR]  (d-major)

    const int tid  = threadIdx.x;
    const int lane = tid & 31;
    const int wid  = tid >> 5;             // 0..3
    const int gq   = lane >> 2;
    const int jq   = lane & 3;
    const int ma   = wid * 32;
    const int mb   = ma + 16;
    const int bh   = blockIdx.y;
    const int q0   = blockIdx.x * 128;
    const int b    = bh / Hh;
    const int h    = bh - b * Hh;

    const float* Qbh = Q + (size_t)bh * Nn * DH;
    const float* Kbh = K + (size_t)bh * Nn * DH;
    const float* Vbh = V + (size_t)bh * Nn * DH;

    // stage Q tile (128x64) raw (pre-rounded tf32 bits)
    #pragma unroll
    for (int p = 0; p < 16; p++) {
        const int idx = tid + p * 128;     // 0..2047
        const int row = idx >> 4;
        const int c4  = (idx & 15) * 4;
        *(uint4*)&Qs[row * FSTR + c4] = *(const uint4*)&Qbh[(size_t)(q0 + row) * DH + c4];
    }

    float o[2][8][4];
    float mx[2][2], ll[2][2];
    #pragma unroll
    for (int bkl = 0; bkl < 2; bkl++) {
        mx[bkl][0] = mx[bkl][1] = -1e30f;
        ll[bkl][0] = ll[bkl][1] = 0.f;
        #pragma unroll
        for (int t = 0; t < 8; t++)
            #pragma unroll
            for (int j = 0; j < 4; j++) o[bkl][t][j] = 0.f;
    }

    for (int k0 = 0; k0 < Nn; k0 += 64) {
        __syncthreads();
        // stage K tile (64x64) raw
        #pragma unroll
        for (int p = 0; p < 8; p++) {
            const int idx = tid + p * 128;
            const int row = idx >> 4;
            const int c4  = (idx & 15) * 4;
            *(uint4*)&Ks[row * FSTR + c4] = *(const uint4*)&Kbh[(size_t)(k0 + row) * DH + c4];
        }
        // stage V transposed: Vt[d][k] raw
        #pragma unroll
        for (int p = 0; p < 8; p++) {
            const int idx = tid + p * 128;
            const int kk  = idx & 63;
            const int d0  = (idx >> 6) * 4;
            uint4 vv = *(const uint4*)&Vbh[(size_t)(k0 + kk) * DH + d0];
            Vt[(d0 + 0) * FSTR + kk] = vv.x;
            Vt[(d0 + 1) * FSTR + kk] = vv.y;
            Vt[(d0 + 2) * FSTR + kk] = vv.z;
            Vt[(d0 + 3) * FSTR + kk] = vv.w;
        }
        __syncthreads();

        // ---- S = Q K^T for both m-blocks (B loaded once) ----
        float s0[8][4], s1[8][4];
        #pragma unroll
        for (int t = 0; t < 8; t++)
            #pragma unroll
            for (int j = 0; j < 4; j++) { s0[t][j] = 0.f; s1[t][j] = 0.f; }

        #pragma unroll
        for (int g = 0; g < 2; g++) {
            #pragma unroll
            for (int half = 0; half < 2; half++) {
                const int kc = g * 32 + half * 4 + jq * 8;
                uint4 a00 = *(const uint4*)&Qs[(ma + gq) * FSTR + kc];
                uint4 a01 = *(const uint4*)&Qs[(ma + gq + 8) * FSTR + kc];
                uint4 a10 = *(const uint4*)&Qs[(mb + gq) * FSTR + kc];
                uint4 a11 = *(const uint4*)&Qs[(mb + gq + 8) * FSTR + kc];
                #pragma unroll
                for (int t = 0; t < 8; t++) {
                    uint4 bv = *(const uint4*)&Ks[(t * 8 + gq) * FSTR + kc];
                    mma_tf32(s0[t], a00.x, a01.x, a00.y, a01.y, bv.x, bv.y);
                    mma_tf32(s0[t], a00.z, a01.z, a00.w, a01.w, bv.z, bv.w);
                    mma_tf32(s1[t], a10.x, a11.x, a10.y, a11.y, bv.x, bv.y);
                    mma_tf32(s1[t], a10.z, a11.z, a10.w, a11.w, bv.z, bv.w);
                }
            }
        }

        // ---- online softmax per m-block ----
        #pragma unroll
        for (int bkl = 0; bkl < 2; bkl++) {
            float (*s)[4] = bkl ? s1 : s0;
            const int mrow = bkl ? mb : ma;
            float smax_lo = -1e30f, smax_hi = -1e30f;
            #pragma unroll
            for (int t = 0; t < 8; t++) {
                smax_lo = fmaxf(smax_lo, fmaxf(s[t][0], s[t][1]));
                smax_hi = fmaxf(smax_hi, fmaxf(s[t][2], s[t][3]));
            }
            #pragma unroll
            for (int off = 1; off <= 2; off <<= 1) {
                smax_lo = fmaxf(smax_lo, __shfl_xor_sync(0xffffffffu, smax_lo, off));
                smax_hi = fmaxf(smax_hi, __shfl_xor_sync(0xffffffffu, smax_hi, off));
            }
            const float mn_lo = fmaxf(mx[bkl][0], smax_lo);
            const float mn_hi = fmaxf(mx[bkl][1], smax_hi);
            const float cr_lo = __expf(mx[bkl][0] - mn_lo);
            const float cr_hi = __expf(mx[bkl][1] - mn_hi);
            mx[bkl][0] = mn_lo; mx[bkl][1] = mn_hi;

            float ls_lo = 0.f, ls_hi = 0.f;
            #pragma unroll
            for (int t = 0; t < 8; t++) {
                float p0 = __expf(s[t][0] - mn_lo);
                float p1 = __expf(s[t][1] - mn_lo);
                float p2 = __expf(s[t][2] - mn_hi);
                float p3 = __expf(s[t][3] - mn_hi);
                ls_lo += p0 + p1;  ls_hi += p2 + p3;
                const int col = t * 8 + 2 * jq;
                Ps[(mrow + gq) * FSTR + col]         = cvt_tf32(p0);
                Ps[(mrow + gq) * FSTR + col + 1]     = cvt_tf32(p1);
                Ps[(mrow + gq + 8) * FSTR + col]     = cvt_tf32(p2);
                Ps[(mrow + gq + 8) * FSTR + col + 1] = cvt_tf32(p3);
            }
            #pragma unroll
            for (int off = 1; off <= 2; off <<= 1) {
                ls_lo += __shfl_xor_sync(0xffffffffu, ls_lo, off);
                ls_hi += __shfl_xor_sync(0xffffffffu, ls_hi, off);
            }
            ll[bkl][0] = ll[bkl][0] * cr_lo + ls_lo;
            ll[bkl][1] = ll[bkl][1] * cr_hi + ls_hi;
            #pragma unroll
            for (int t = 0; t < 8; t++) {
                o[bkl][t][0] *= cr_lo; o[bkl][t][1] *= cr_lo;
                o[bkl][t][2] *= cr_hi; o[bkl][t][3] *= cr_hi;
            }
        }
        __syncwarp();

        // ---- O += P V (B loaded once, both m-blocks) ----
        #pragma unroll
        for (int g = 0; g < 2; g++) {
            #pragma unroll
            for (int half = 0; half < 2; half++) {
                const int kc = g * 32 + half * 4 + jq * 8;
                uint4 a00 = *(const uint4*)&Ps[(ma + gq) * FSTR + kc];
                uint4 a01 = *(const uint4*)&Ps[(ma + gq + 8) * FSTR + kc];
                uint4 a10 = *(const uint4*)&Ps[(mb + gq) * FSTR + kc];
                uint4 a11 = *(const uint4*)&Ps[(mb + gq + 8) * FSTR + kc];
                #pragma unroll
                for (int t = 0; t < 8; t++) {
                    uint4 bv = *(const uint4*)&Vt[(t * 8 + gq) * FSTR + kc];
                    mma_tf32(o[0][t], a00.x, a01.x, a00.y, a01.y, bv.x, bv.y);
                    mma_tf32(o[0][t], a00.z, a01.z, a00.w, a01.w, bv.z, bv.w);
                    mma_tf32(o[1][t], a10.x, a11.x, a10.y, a11.y, bv.x, bv.y);
                    mma_tf32(o[1][t], a10.z, a11.z, a10.w, a11.w, bv.z, bv.w);
                }
            }
        }
    }

    // epilogue: normalize, round to tf32, write AO[b][n][h*64+d]
    #pragma unroll
    for (int bkl = 0; bkl < 2; bkl++) {
        const int mrow = bkl ? mb : ma;
        const float inv_lo = 1.0f / ll[bkl][0];
        const float inv_hi = 1.0f / ll[bkl][1];
        #pragma unroll
        for (int t = 0; t < 8; t++) {
            const int col = h * DH + t * 8 + 2 * jq;
            const size_t r0 = (size_t)(b * Nn + q0 + mrow + gq) * Dd + col;
            const size_t r1 = (size_t)(b * Nn + q0 + mrow + gq + 8) * Dd + col;
            *(float2*)&AO[r0] = make_float2(rnd_tf32(o[bkl][t][0] * inv_lo),
                                            rnd_tf32(o[bkl][t][1] * inv_lo));
            *(float2*)&AO[r1] = make_float2(rnd_tf32(o[bkl][t][2] * inv_hi),
                                            rnd_tf32(o[bkl][t][3] * inv_hi));
        }
    }
}

// ---------------- launch ----------------
extern "C" void kernel_launch(void* const* d_in, const int* in_sizes, int n_in,
                              void* d_out, int out_size)
{
    const float* x      = (const float*)d_in[0];
    const float* coords = (const float*)d_in[1];
    const float* gamma  = (const float*)d_in[2];
    const float* beta   = (const float*)d_in[3];
    const float* wqkv   = (const float*)d_in[4];
    const float* wout   = (const float*)d_in[5];
    float* out = (float*)d_out;

    float *xn, *qkv, *q, *k, *v, *ao, *wq, *wo;
    cudaGetSymbolAddress((void**)&xn,  g_xn);
    cudaGetSymbolAddress((void**)&qkv, g_qkv);
    cudaGetSymbolAddress((void**)&q,   g_q);
    cudaGetSymbolAddress((void**)&k,   g_k);
    cudaGetSymbolAddress((void**)&v,   g_v);
    cudaGetSymbolAddress((void**)&ao,  g_ao);
    cudaGetSymbolAddress((void**)&wq,  g_wq);
    cudaGetSymbolAddress((void**)&wo,  g_wo);

    const int gemm_smem = 2 * 2 * TILE_F * (int)sizeof(float);          // 73728 B
    const int attn_smem = (2 * 128 * FSTR + 2 * 64 * FSTR) * 4;         // 104448 B
    cudaFuncSetAttribute(gemm_mma, cudaFuncAttributeMaxDynamicSharedMemorySize, gemm_smem);
    cudaFuncSetAttribute(attn_mma, cudaFuncAttributeMaxDynamicSharedMemorySize, attn_smem);

    const int nwq = 3 * Dd * Dd, nwo = Dd * Dd;
    cvtw_kernel<<<nwq / 1024, 256>>>(wqkv, wq, nwq);
    cvtw_kernel<<<nwo / 1024, 256>>>(wout, wo, nwo);
    ln_kernel<<<M_TOT, 256>>>(x, gamma, beta, xn);
    gemm_mma<<<dim3(3 * Dd / 128, M_TOT / 128), 128, gemm_smem>>>(xn, wq, qkv, 3 * Dd, Dd);
    rope_kernel<<<M_TOT, 256>>>(qkv, coords, q, k, v);
    attn_mma<<<dim3(Nn / 128, BH), 128, attn_smem>>>(q, k, v, ao);
    gemm_mma<<<dim3(Dd / 128, M_TOT / 128), 128, gemm_smem>>>(ao, wo, out, Dd, Dd);
}

// round 8
// speedup vs baseline: 1.2647x; 1.1917x over previous
#include <cuda_runtime.h>
#include <math.h>
#include <cstdint>

#define Bb 4
#define Nn 2048
#define Dd 768
#define Hh 12
#define DH 64
#define M_TOT (Bb*Nn)      /* 8192 */
#define BH (Bb*Hh)         /* 48   */

// ---------------- scratch (device globals; no allocs allowed) ----------------
__device__ float g_xn  [(size_t)M_TOT * Dd];
__device__ float g_qkv [(size_t)M_TOT * 3 * Dd];
__device__ float g_q   [(size_t)BH * Nn * DH];
__device__ float g_k   [(size_t)BH * Nn * DH];
__device__ float g_v   [(size_t)BH * Nn * DH];   // stored TRANSPOSED: [bh][d][n]
__device__ float g_ao  [(size_t)M_TOT * Dd];
__device__ float g_wq  [(size_t)3 * Dd * Dd];
__device__ float g_wo  [(size_t)Dd * Dd];

// ======================= helpers =======================
__device__ __forceinline__ uint32_t smem_u32(const void* p) {
    uint32_t a;
    asm("{ .reg .u64 t; cvta.to.shared.u64 t, %1; cvt.u32.u64 %0, t; }" : "=r"(a) : "l"(p));
    return a;
}
__device__ __forceinline__ void cp16(uint32_t dst, const void* src) {
    asm volatile("cp.async.cg.shared.global [%0], [%1], 16;" :: "r"(dst), "l"(src) : "memory");
}
__device__ __forceinline__ uint32_t cvt_tf32(float x) {
    uint32_t r;
    asm("cvt.rna.tf32.f32 %0, %1;" : "=r"(r) : "f"(x));
    return r;
}
__device__ __forceinline__ float rnd_tf32(float x) {
    return __uint_as_float(cvt_tf32(x));
}
__device__ __forceinline__ void mma_tf32(float* c, uint32_t a0, uint32_t a1, uint32_t a2, uint32_t a3,
                                         uint32_t b0, uint32_t b1) {
    asm volatile("mma.sync.aligned.m16n8k8.row.col.f32.tf32.tf32.f32 "
                 "{%0,%1,%2,%3}, {%4,%5,%6,%7}, {%8,%9}, {%0,%1,%2,%3};"
                 : "+f"(c[0]), "+f"(c[1]), "+f"(c[2]), "+f"(c[3])
                 : "r"(a0), "r"(a1), "r"(a2), "r"(a3), "r"(b0), "r"(b1));
}

// ---------------- tf32 rounding pass (weights) ----------------
__global__ __launch_bounds__(256) void cvtw_kernel(const float* __restrict__ src,
                                                   float* __restrict__ dst, int n)
{
    const int i = (blockIdx.x * 256 + threadIdx.x) * 4;
    if (i < n) {
        float4 v = *(const float4*)&src[i];
        v.x = rnd_tf32(v.x); v.y = rnd_tf32(v.y);
        v.z = rnd_tf32(v.z); v.w = rnd_tf32(v.w);
        *(float4*)&dst[i] = v;
    }
}

// ---------------- LayerNorm (writes tf32-rounded) ----------------
__global__ __launch_bounds__(256) void ln_kernel(const float* __restrict__ x,
                                                 const float* __restrict__ gamma,
                                                 const float* __restrict__ beta,
                                                 float* __restrict__ xn)
{
    const int row = blockIdx.x;
    const int t   = threadIdx.x;
    const float* xr = x + (size_t)row * Dd;
    float v0 = xr[t], v1 = xr[t + 256], v2 = xr[t + 512];
    float s  = v0 + v1 + v2;
    float sq = v0*v0 + v1*v1 + v2*v2;
    #pragma unroll
    for (int off = 16; off; off >>= 1) {
        s  += __shfl_xor_sync(0xffffffffu, s,  off);
        sq += __shfl_xor_sync(0xffffffffu, sq, off);
    }
    __shared__ float rs[8], rq[8];
    const int w = t >> 5, lane = t & 31;
    if (lane == 0) { rs[w] = s; rq[w] = sq; }
    __syncthreads();
    if (t == 0) {
        float S = 0.f, Q = 0.f;
        #pragma unroll
        for (int i = 0; i < 8; i++) { S += rs[i]; Q += rq[i]; }
        rs[0] = S; rq[0] = Q;
    }
    __syncthreads();
    const float mu   = rs[0] * (1.0f / 768.0f);
    const float var  = rq[0] * (1.0f / 768.0f) - mu * mu;
    const float rstd = rsqrtf(var + 1e-5f);
    float* xo = xn + (size_t)row * Dd;
    xo[t      ] = rnd_tf32((v0 - mu) * rstd * gamma[t      ] + beta[t      ]);
    xo[t + 256] = rnd_tf32((v1 - mu) * rstd * gamma[t + 256] + beta[t + 256]);
    xo[t + 512] = rnd_tf32((v2 - mu) * rstd * gamma[t + 512] + beta[t + 512]);
}

// ---------------- mma.sync tf32 GEMM: 4 warps, 64x64 warp tiles ----------------
#define ASTR 36
#define TILE_F (128 * ASTR)
__global__ __launch_bounds__(128, 2) void gemm_mma(const float* __restrict__ A,
                                                   const float* __restrict__ W,
                                                   float* __restrict__ C,
                                                   int Np, int K)
{
    extern __shared__ __align__(16) float sg[];
    const int tid  = threadIdx.x;
    const int lane = tid & 31;
    const int wid  = tid >> 5;
    const int wm   = wid >> 1;
    const int wn   = wid & 1;
    const int gq   = lane >> 2;
    const int jq   = lane & 3;
    const int bm   = blockIdx.y * 128;
    const int bn   = blockIdx.x * 128;

    float acc[4][8][4];
    #pragma unroll
    for (int i = 0; i < 4; i++)
        #pragma unroll
        for (int j = 0; j < 8; j++)
            #pragma unroll
            for (int q = 0; q < 4; q++) acc[i][j][q] = 0.f;

    const int nCh = K / 32;

#define LOAD_STAGE(IT, S) do {                                                \
    const float* Ab = A + (size_t)bm * K + (IT) * 32;                         \
    const float* Wb = W + (size_t)bn * K + (IT) * 32;                         \
    float* As_ = sg + (S) * (2 * TILE_F);                                     \
    float* Bs_ = As_ + TILE_F;                                                \
    _Pragma("unroll")                                                         \
    for (int p = 0; p < 8; p++) {                                             \
        const int idx = tid + p * 128;                                        \
        const int row = idx >> 3;                                             \
        const int c4  = (idx & 7) * 4;                                        \
        cp16(smem_u32(&As_[row * ASTR + c4]), &Ab[(size_t)row * K + c4]);     \
        cp16(smem_u32(&Bs_[row * ASTR + c4]), &Wb[(size_t)row * K + c4]);     \
    }                                                                         \
    asm volatile("cp.async.commit_group;" ::: "memory");                      \
} while (0)

    LOAD_STAGE(0, 0);

    for (int it = 0; it < nCh; it++) {
        const int s = it & 1;
        if (it + 1 < nCh) {
            LOAD_STAGE(it + 1, s ^ 1);
            asm volatile("cp.async.wait_group 1;" ::: "memory");
        } else {
            asm volatile("cp.async.wait_group 0;" ::: "memory");
        }
        __syncthreads();

        const float* As_ = sg + s * (2 * TILE_F);
        const float* Bs_ = As_ + TILE_F;

        #pragma unroll
        for (int half = 0; half < 2; half++) {
            const int kc = jq * 8 + half * 4;
            uint4 afr[8];
            #pragma unroll
            for (int mf = 0; mf < 4; mf++) {
                const int m = wm * 64 + mf * 16 + gq;
                afr[2 * mf]     = *(const uint4*)&As_[m * ASTR + kc];
                afr[2 * mf + 1] = *(const uint4*)&As_[(m + 8) * ASTR + kc];
            }
            #pragma unroll
            for (int ng = 0; ng < 2; ng++) {
                uint4 bfr[4];
                #pragma unroll
                for (int j = 0; j < 4; j++) {
                    const int n = wn * 64 + (ng * 4 + j) * 8 + gq;
                    bfr[j] = *(const uint4*)&Bs_[n * ASTR + kc];
                }
                #pragma unroll
                for (int mf = 0; mf < 4; mf++) {
                    #pragma unroll
                    for (int j = 0; j < 4; j++) {
                        float* a = acc[mf][ng * 4 + j];
                        mma_tf32(a, afr[2*mf].x, afr[2*mf+1].x, afr[2*mf].y, afr[2*mf+1].y,
                                 bfr[j].x, bfr[j].y);
                        mma_tf32(a, afr[2*mf].z, afr[2*mf+1].z, afr[2*mf].w, afr[2*mf+1].w,
                                 bfr[j].z, bfr[j].w);
                    }
                }
            }
        }
        __syncthreads();
    }

    #pragma unroll
    for (int mf = 0; mf < 4; mf++) {
        const int r = bm + wm * 64 + mf * 16 + gq;
        #pragma unroll
        for (int nf = 0; nf < 8; nf++) {
            const int n0 = bn + wn * 64 + nf * 8 + 2 * jq;
            *(float2*)&C[(size_t)r * Np + n0]       = make_float2(acc[mf][nf][0], acc[mf][nf][1]);
            *(float2*)&C[(size_t)(r + 8) * Np + n0] = make_float2(acc[mf][nf][2], acc[mf][nf][3]);
        }
    }
#undef LOAD_STAGE
}

// ---------------- RoPE + head split ----------------
// Q scaled by 0.125*log2(e) (exp2-domain softmax); V written TRANSPOSED [bh][d][n].
__global__ __launch_bounds__(256) void rope_kernel(const float* __restrict__ qkv,
                                                   const float* __restrict__ coords,
                                                   float* __restrict__ Qo,
                                                   float* __restrict__ Ko,
                                                   float* __restrict__ Vo)
{
    const int m = blockIdx.x;
    const int b = m >> 11;
    const int n = m & 2047;
    const float c0 = coords[m * 2 + 0];
    const float c1 = coords[m * 2 + 1];
    const float* src = qkv + (size_t)m * (3 * Dd);

    for (int t = threadIdx.x; t < 3 * Dd; t += 256) {
        const int which = t / Dd;
        const int r     = t - which * Dd;
        const int h     = r >> 6;
        const int d     = r & 63;
        float val;
        if (which == 2) {
            val = src[t];
        } else {
            const int slice = d >> 5;
            const int dl    = d & 31;
            const int j     = dl & 15;
            const int isodd = dl >> 4;
            const float coord = slice ? c1 : c0;
            const float invf  = exp2f(-13.0f * (float)j * (1.0f / 16.0f));
            const float f  = coord * invf;
            const float cs = cosf(f);
            const float sn = sinf(f);
            const int   e  = which * Dd + h * 64 + slice * 32 + 2 * j;
            const float t1 = src[e];
            const float t2 = src[e + 1];
            val = isodd ? (t1 * sn + t2 * cs) : (t1 * cs - t2 * sn);
            if (which == 0) val *= 0.18033688011112042f;   // 0.125 * log2(e)
        }
        if (which == 2) {
            Vo[((size_t)(b * Hh + h) * DH + d) * Nn + n] = rnd_tf32(val);
        } else {
            float* dst = (which == 0) ? Qo : Ko;
            dst[((size_t)(b * Hh + h) * Nn + n) * DH + d] = rnd_tf32(val);
        }
    }
}

// ---------------- mma.sync tf32 flash attention ----------------
// Bq=128, Bk=64, 128 threads. Q lives in registers (A-frags, loaded once).
// K/V(transposed) double-buffered via cp.async. exp2-domain softmax.
#define FSTR 68
__global__ __launch_bounds__(128, 2) void attn_mma(const float* __restrict__ Q,
                                                   const float* __restrict__ K,
                                                   const float* __restrict__ VT,
                                                   float* __restrict__ AO)
{
    extern __shared__ __align__(16) uint32_t sa[];
    uint32_t* Ps = sa;                     // [128][FSTR]
    uint32_t* KV = Ps + 128 * FSTR;        // 2 stages x (K[64][FSTR] | Vt[64][FSTR])

    const int tid  = threadIdx.x;
    const int lane = tid & 31;
    const int wid  = tid >> 5;             // 0..3
    const int gq   = lane >> 2;
    const int jq   = lane & 3;
    const int ma   = wid * 32;
    const int mb   = ma + 16;
    const int bh   = blockIdx.y;
    const int q0   = blockIdx.x * 128;
    const int b    = bh / Hh;
    const int h    = bh - b * Hh;

    const float* Qbh  = Q  + (size_t)bh * Nn * DH;
    const float* Kbh  = K  + (size_t)bh * Nn * DH;
    const float* VTbh = VT + (size_t)bh * DH * Nn;

    // Q A-fragments in registers (once). kc covers the k-permuted layout.
    uint4 qa[2][4][2];
    #pragma unroll
    for (int bkl = 0; bkl < 2; bkl++) {
        const int r0 = q0 + (bkl ? mb : ma) + gq;
        #pragma unroll
        for (int gh = 0; gh < 4; gh++) {
            const int kc = (gh >> 1) * 32 + (gh & 1) * 4 + jq * 8;
            qa[bkl][gh][0] = *(const uint4*)&Qbh[(size_t)r0 * DH + kc];
            qa[bkl][gh][1] = *(const uint4*)&Qbh[(size_t)(r0 + 8) * DH + kc];
        }
    }

    float o[2][8][4];
    float mx[2][2], ll[2][2];
    #pragma unroll
    for (int bkl = 0; bkl < 2; bkl++) {
        mx[bkl][0] = mx[bkl][1] = -1e30f;
        ll[bkl][0] = ll[bkl][1] = 0.f;
        #pragma unroll
        for (int t = 0; t < 8; t++)
            #pragma unroll
            for (int j = 0; j < 4; j++) o[bkl][t][j] = 0.f;
    }

#define PREFETCH(IT, S) do {                                                       \
    uint32_t* Kd = KV + (S) * (128 * FSTR);                                        \
    uint32_t* Vd = Kd + 64 * FSTR;                                                 \
    _Pragma("unroll")                                                              \
    for (int p = 0; p < 8; p++) {                                                  \
        const int idx = tid + p * 128;                                             \
        const int row = idx >> 4;                                                  \
        const int c4  = (idx & 15) * 4;                                            \
        cp16(smem_u32(&Kd[row * FSTR + c4]), &Kbh[(size_t)((IT) * 64 + row) * DH + c4]); \
        cp16(smem_u32(&Vd[row * FSTR + c4]), &VTbh[(size_t)row * Nn + (IT) * 64 + c4]);  \
    }                                                                              \
    asm volatile("cp.async.commit_group;" ::: "memory");                           \
} while (0)

    PREFETCH(0, 0);

    const int nT = Nn / 64;
    for (int it = 0; it < nT; it++) {
        const int s = it & 1;
        if (it + 1 < nT) {
            PREFETCH(it + 1, s ^ 1);
            asm volatile("cp.async.wait_group 1;" ::: "memory");
        } else {
            asm volatile("cp.async.wait_group 0;" ::: "memory");
        }
        __syncthreads();
        const uint32_t* Ksm = KV + s * (128 * FSTR);
        const uint32_t* Vsm = Ksm + 64 * FSTR;

        // ---- S = Q K^T (Q in regs) ----
        float s0[8][4], s1[8][4];
        #pragma unroll
        for (int t = 0; t < 8; t++)
            #pragma unroll
            for (int j = 0; j < 4; j++) { s0[t][j] = 0.f; s1[t][j] = 0.f; }

        #pragma unroll
        for (int gh = 0; gh < 4; gh++) {
            const int kc = (gh >> 1) * 32 + (gh & 1) * 4 + jq * 8;
            const uint4 a00 = qa[0][gh][0], a01 = qa[0][gh][1];
            const uint4 a10 = qa[1][gh][0], a11 = qa[1][gh][1];
            #pragma unroll
            for (int t = 0; t < 8; t++) {
                uint4 bv = *(const uint4*)&Ksm[(t * 8 + gq) * FSTR + kc];
                mma_tf32(s0[t], a00.x, a01.x, a00.y, a01.y, bv.x, bv.y);
                mma_tf32(s0[t], a00.z, a01.z, a00.w, a01.w, bv.z, bv.w);
                mma_tf32(s1[t], a10.x, a11.x, a10.y, a11.y, bv.x, bv.y);
                mma_tf32(s1[t], a10.z, a11.z, a10.w, a11.w, bv.z, bv.w);
            }
        }

        // ---- online softmax per m-block (log2 domain) ----
        #pragma unroll
        for (int bkl = 0; bkl < 2; bkl++) {
            float (*s)[4] = bkl ? s1 : s0;
            const int mrow = bkl ? mb : ma;
            float smax_lo = -1e30f, smax_hi = -1e30f;
            #pragma unroll
            for (int t = 0; t < 8; t++) {
                smax_lo = fmaxf(smax_lo, fmaxf(s[t][0], s[t][1]));
                smax_hi = fmaxf(smax_hi, fmaxf(s[t][2], s[t][3]));
            }
            #pragma unroll
            for (int off = 1; off <= 2; off <<= 1) {
                smax_lo = fmaxf(smax_lo, __shfl_xor_sync(0xffffffffu, smax_lo, off));
                smax_hi = fmaxf(smax_hi, __shfl_xor_sync(0xffffffffu, smax_hi, off));
            }
            const float mn_lo = fmaxf(mx[bkl][0], smax_lo);
            const float mn_hi = fmaxf(mx[bkl][1], smax_hi);
            const float cr_lo = exp2f(mx[bkl][0] - mn_lo);
            const float cr_hi = exp2f(mx[bkl][1] - mn_hi);
            mx[bkl][0] = mn_lo; mx[bkl][1] = mn_hi;

            float ls_lo = 0.f, ls_hi = 0.f;
            #pragma unroll
            for (int t = 0; t < 8; t++) {
                float p0 = exp2f(s[t][0] - mn_lo);
                float p1 = exp2f(s[t][1] - mn_lo);
                float p2 = exp2f(s[t][2] - mn_hi);
                float p3 = exp2f(s[t][3] - mn_hi);
                ls_lo += p0 + p1;  ls_hi += p2 + p3;
                const int col = t * 8 + 2 * jq;
                *(uint2*)&Ps[(mrow + gq) * FSTR + col]     = make_uint2(cvt_tf32(p0), cvt_tf32(p1));
                *(uint2*)&Ps[(mrow + gq + 8) * FSTR + col] = make_uint2(cvt_tf32(p2), cvt_tf32(p3));
            }
            #pragma unroll
            for (int off = 1; off <= 2; off <<= 1) {
                ls_lo += __shfl_xor_sync(0xffffffffu, ls_lo, off);
                ls_hi += __shfl_xor_sync(0xffffffffu, ls_hi, off);
            }
            ll[bkl][0] = ll[bkl][0] * cr_lo + ls_lo;
            ll[bkl][1] = ll[bkl][1] * cr_hi + ls_hi;
            #pragma unroll
            for (int t = 0; t < 8; t++) {
                o[bkl][t][0] *= cr_lo; o[bkl][t][1] *= cr_lo;
                o[bkl][t][2] *= cr_hi; o[bkl][t][3] *= cr_hi;
            }
        }
        __syncwarp();

        // ---- O += P V ----
        #pragma unroll
        for (int gh = 0; gh < 4; gh++) {
            const int kc = (gh >> 1) * 32 + (gh & 1) * 4 + jq * 8;
            uint4 a00 = *(const uint4*)&Ps[(ma + gq) * FSTR + kc];
            uint4 a01 = *(const uint4*)&Ps[(ma + gq + 8) * FSTR + kc];
            uint4 a10 = *(const uint4*)&Ps[(mb + gq) * FSTR + kc];
            uint4 a11 = *(const uint4*)&Ps[(mb + gq + 8) * FSTR + kc];
            #pragma unroll
            for (int t = 0; t < 8; t++) {
                uint4 bv = *(const uint4*)&Vsm[(t * 8 + gq) * FSTR + kc];
                mma_tf32(o[0][t], a00.x, a01.x, a00.y, a01.y, bv.x, bv.y);
                mma_tf32(o[0][t], a00.z, a01.z, a00.w, a01.w, bv.z, bv.w);
                mma_tf32(o[1][t], a10.x, a11.x, a10.y, a11.y, bv.x, bv.y);
                mma_tf32(o[1][t], a10.z, a11.z, a10.w, a11.w, bv.z, bv.w);
            }
        }
        __syncthreads();
    }
#undef PREFETCH

    // epilogue: normalize, round to tf32, write AO[b][n][h*64+d]
    #pragma unroll
    for (int bkl = 0; bkl < 2; bkl++) {
        const int mrow = bkl ? mb : ma;
        const float inv_lo = 1.0f / ll[bkl][0];
        const float inv_hi = 1.0f / ll[bkl][1];
        #pragma unroll
        for (int t = 0; t < 8; t++) {
            const int col = h * DH + t * 8 + 2 * jq;
            const size_t r0 = (size_t)(b * Nn + q0 + mrow + gq) * Dd + col;
            const size_t r1 = (size_t)(b * Nn + q0 + mrow + gq + 8) * Dd + col;
            *(float2*)&AO[r0] = make_float2(rnd_tf32(o[bkl][t][0] * inv_lo),
                                            rnd_tf32(o[bkl][t][1] * inv_lo));
            *(float2*)&AO[r1] = make_float2(rnd_tf32(o[bkl][t][2] * inv_hi),
                                            rnd_tf32(o[bkl][t][3] * inv_hi));
        }
    }
}

// ---------------- launch ----------------
extern "C" void kernel_launch(void* const* d_in, const int* in_sizes, int n_in,
                              void* d_out, int out_size)
{
    const float* x      = (const float*)d_in[0];
    const float* coords = (const float*)d_in[1];
    const float* gamma  = (const float*)d_in[2];
    const float* beta   = (const float*)d_in[3];
    const float* wqkv   = (const float*)d_in[4];
    const float* wout   = (const float*)d_in[5];
    float* out = (float*)d_out;

    float *xn, *qkv, *q, *k, *v, *ao, *wq, *wo;
    cudaGetSymbolAddress((void**)&xn,  g_xn);
    cudaGetSymbolAddress((void**)&qkv, g_qkv);
    cudaGetSymbolAddress((void**)&q,   g_q);
    cudaGetSymbolAddress((void**)&k,   g_k);
    cudaGetSymbolAddress((void**)&v,   g_v);
    cudaGetSymbolAddress((void**)&ao,  g_ao);
    cudaGetSymbolAddress((void**)&wq,  g_wq);
    cudaGetSymbolAddress((void**)&wo,  g_wo);

    const int gemm_smem = 2 * 2 * TILE_F * (int)sizeof(float);   // 73728 B
    const int attn_smem = 3 * 128 * FSTR * (int)sizeof(float);   // 104448 B
    cudaFuncSetAttribute(gemm_mma, cudaFuncAttributeMaxDynamicSharedMemorySize, gemm_smem);
    cudaFuncSetAttribute(attn_mma, cudaFuncAttributeMaxDynamicSharedMemorySize, attn_smem);

    const int nwq = 3 * Dd * Dd, nwo = Dd * Dd;
    cvtw_kernel<<<nwq / 1024, 256>>>(wqkv, wq, nwq);
    cvtw_kernel<<<nwo / 1024, 256>>>(wout, wo, nwo);
    ln_kernel<<<M_TOT, 256>>>(x, gamma, beta, xn);
    gemm_mma<<<dim3(3 * Dd / 128, M_TOT / 128), 128, gemm_smem>>>(xn, wq, qkv, 3 * Dd, Dd);
    rope_kernel<<<M_TOT, 256>>>(qkv, coords, q, k, v);
    attn_mma<<<dim3(Nn / 128, BH), 128, attn_smem>>>(q, k, v, ao);
    gemm_mma<<<dim3(Dd / 128, M_TOT / 128), 128, gemm_smem>>>(ao, wo, out, Dd, Dd);
}

// round 9
// speedup vs baseline: 1.3044x; 1.0314x over previous
#include <cuda_runtime.h>
#include <math.h>
#include <cstdint>

#define Bb 4
#define Nn 2048
#define Dd 768
#define Hh 12
#define DH 64
#define M_TOT (Bb*Nn)      /* 8192 */
#define BH (Bb*Hh)         /* 48   */

// ---------------- scratch (device globals; no allocs allowed) ----------------
__device__ float g_xn  [(size_t)M_TOT * Dd];
__device__ float g_qkv [(size_t)M_TOT * 3 * Dd];
__device__ float g_q   [(size_t)BH * Nn * DH];
__device__ float g_k   [(size_t)BH * Nn * DH];
__device__ float g_v   [(size_t)BH * Nn * DH];   // stored TRANSPOSED: [bh][d][n]
__device__ float g_ao  [(size_t)M_TOT * Dd];
__device__ float g_wq  [(size_t)3 * Dd * Dd];
__device__ float g_wo  [(size_t)Dd * Dd];

// ======================= helpers =======================
__device__ __forceinline__ uint32_t smem_u32(const void* p) {
    uint32_t a;
    asm("{ .reg .u64 t; cvta.to.shared.u64 t, %1; cvt.u32.u64 %0, t; }" : "=r"(a) : "l"(p));
    return a;
}
__device__ __forceinline__ void cp16(uint32_t dst, const void* src) {
    asm volatile("cp.async.cg.shared.global [%0], [%1], 16;" :: "r"(dst), "l"(src) : "memory");
}
__device__ __forceinline__ uint32_t cvt_tf32(float x) {
    uint32_t r;
    asm("cvt.rna.tf32.f32 %0, %1;" : "=r"(r) : "f"(x));
    return r;
}
__device__ __forceinline__ float rnd_tf32(float x) {
    return __uint_as_float(cvt_tf32(x));
}
__device__ __forceinline__ void mma_tf32(float* c, uint32_t a0, uint32_t a1, uint32_t a2, uint32_t a3,
                                         uint32_t b0, uint32_t b1) {
    asm volatile("mma.sync.aligned.m16n8k8.row.col.f32.tf32.tf32.f32 "
                 "{%0,%1,%2,%3}, {%4,%5,%6,%7}, {%8,%9}, {%0,%1,%2,%3};"
                 : "+f"(c[0]), "+f"(c[1]), "+f"(c[2]), "+f"(c[3])
                 : "r"(a0), "r"(a1), "r"(a2), "r"(a3), "r"(b0), "r"(b1));
}

// ---------------- tf32 rounding pass (weights) ----------------
__global__ __launch_bounds__(256) void cvtw_kernel(const float* __restrict__ src,
                                                   float* __restrict__ dst, int n)
{
    const int i = (blockIdx.x * 256 + threadIdx.x) * 4;
    if (i < n) {
        float4 v = *(const float4*)&src[i];
        v.x = rnd_tf32(v.x); v.y = rnd_tf32(v.y);
        v.z = rnd_tf32(v.z); v.w = rnd_tf32(v.w);
        *(float4*)&dst[i] = v;
    }
}

// ---------------- LayerNorm (writes tf32-rounded) ----------------
__global__ __launch_bounds__(256) void ln_kernel(const float* __restrict__ x,
                                                 const float* __restrict__ gamma,
                                                 const float* __restrict__ beta,
                                                 float* __restrict__ xn)
{
    const int row = blockIdx.x;
    const int t   = threadIdx.x;
    const float* xr = x + (size_t)row * Dd;
    float v0 = xr[t], v1 = xr[t + 256], v2 = xr[t + 512];
    float s  = v0 + v1 + v2;
    float sq = v0*v0 + v1*v1 + v2*v2;
    #pragma unroll
    for (int off = 16; off; off >>= 1) {
        s  += __shfl_xor_sync(0xffffffffu, s,  off);
        sq += __shfl_xor_sync(0xffffffffu, sq, off);
    }
    __shared__ float rs[8], rq[8];
    const int w = t >> 5, lane = t & 31;
    if (lane == 0) { rs[w] = s; rq[w] = sq; }
    __syncthreads();
    if (t == 0) {
        float S = 0.f, Q = 0.f;
        #pragma unroll
        for (int i = 0; i < 8; i++) { S += rs[i]; Q += rq[i]; }
        rs[0] = S; rq[0] = Q;
    }
    __syncthreads();
    const float mu   = rs[0] * (1.0f / 768.0f);
    const float var  = rq[0] * (1.0f / 768.0f) - mu * mu;
    const float rstd = rsqrtf(var + 1e-5f);
    float* xo = xn + (size_t)row * Dd;
    xo[t      ] = rnd_tf32((v0 - mu) * rstd * gamma[t      ] + beta[t      ]);
    xo[t + 256] = rnd_tf32((v1 - mu) * rstd * gamma[t + 256] + beta[t + 256]);
    xo[t + 512] = rnd_tf32((v2 - mu) * rstd * gamma[t + 512] + beta[t + 512]);
}

// ---------------- mma.sync tf32 GEMM: 4 warps, 64x64 warp tiles, 3-stage ----------------
#define ASTR 36
#define TILE_F (128 * ASTR)
__global__ __launch_bounds__(128, 2) void gemm_mma(const float* __restrict__ A,
                                                   const float* __restrict__ W,
                                                   float* __restrict__ C,
                                                   int Np, int K)
{
    extern __shared__ __align__(16) float sg[];
    const int tid  = threadIdx.x;
    const int lane = tid & 31;
    const int wid  = tid >> 5;
    const int wm   = wid >> 1;
    const int wn   = wid & 1;
    const int gq   = lane >> 2;
    const int jq   = lane & 3;
    const int bm   = blockIdx.y * 128;
    const int bn   = blockIdx.x * 128;

    float acc[4][8][4];
    #pragma unroll
    for (int i = 0; i < 4; i++)
        #pragma unroll
        for (int j = 0; j < 8; j++)
            #pragma unroll
            for (int q = 0; q < 4; q++) acc[i][j][q] = 0.f;

    const int nCh = K / 32;

#define LOAD_STAGE(IT, S) do {                                                \
    const float* Ab = A + (size_t)bm * K + (IT) * 32;                         \
    const float* Wb = W + (size_t)bn * K + (IT) * 32;                         \
    float* As_ = sg + (S) * (2 * TILE_F);                                     \
    float* Bs_ = As_ + TILE_F;                                                \
    _Pragma("unroll")                                                         \
    for (int p = 0; p < 8; p++) {                                             \
        const int idx = tid + p * 128;                                        \
        const int row = idx >> 3;                                             \
        const int c4  = (idx & 7) * 4;                                        \
        cp16(smem_u32(&As_[row * ASTR + c4]), &Ab[(size_t)row * K + c4]);     \
        cp16(smem_u32(&Bs_[row * ASTR + c4]), &Wb[(size_t)row * K + c4]);     \
    }                                                                         \
    asm volatile("cp.async.commit_group;" ::: "memory");                      \
} while (0)

    LOAD_STAGE(0, 0);
    LOAD_STAGE(1, 1);

    int s = 0, s2 = 2;
    for (int it = 0; it < nCh; it++) {
        if (it + 1 < nCh) {
            asm volatile("cp.async.wait_group 1;" ::: "memory");
        } else {
            asm volatile("cp.async.wait_group 0;" ::: "memory");
        }
        __syncthreads();
        if (it + 2 < nCh) LOAD_STAGE(it + 2, s2);

        const float* As_ = sg + s * (2 * TILE_F);
        const float* Bs_ = As_ + TILE_F;

        #pragma unroll
        for (int half = 0; half < 2; half++) {
            const int kc = jq * 8 + half * 4;
            uint4 afr[8];
            #pragma unroll
            for (int mf = 0; mf < 4; mf++) {
                const int m = wm * 64 + mf * 16 + gq;
                afr[2 * mf]     = *(const uint4*)&As_[m * ASTR + kc];
                afr[2 * mf + 1] = *(const uint4*)&As_[(m + 8) * ASTR + kc];
            }
            #pragma unroll
            for (int ng = 0; ng < 2; ng++) {
                uint4 bfr[4];
                #pragma unroll
                for (int j = 0; j < 4; j++) {
                    const int n = wn * 64 + (ng * 4 + j) * 8 + gq;
                    bfr[j] = *(const uint4*)&Bs_[n * ASTR + kc];
                }
                #pragma unroll
                for (int mf = 0; mf < 4; mf++) {
                    #pragma unroll
                    for (int j = 0; j < 4; j++) {
                        float* a = acc[mf][ng * 4 + j];
                        mma_tf32(a, afr[2*mf].x, afr[2*mf+1].x, afr[2*mf].y, afr[2*mf+1].y,
                                 bfr[j].x, bfr[j].y);
                        mma_tf32(a, afr[2*mf].z, afr[2*mf+1].z, afr[2*mf].w, afr[2*mf+1].w,
                                 bfr[j].z, bfr[j].w);
                    }
                }
            }
        }
        s  = (s  == 2) ? 0 : s + 1;
        s2 = (s2 == 2) ? 0 : s2 + 1;
    }

    #pragma unroll
    for (int mf = 0; mf < 4; mf++) {
        const int r = bm + wm * 64 + mf * 16 + gq;
        #pragma unroll
        for (int nf = 0; nf < 8; nf++) {
            const int n0 = bn + wn * 64 + nf * 8 + 2 * jq;
            *(float2*)&C[(size_t)r * Np + n0]       = make_float2(acc[mf][nf][0], acc[mf][nf][1]);
            *(float2*)&C[(size_t)(r + 8) * Np + n0] = make_float2(acc[mf][nf][2], acc[mf][nf][3]);
        }
    }
#undef LOAD_STAGE
}

// ---------------- RoPE + head split ----------------
// Q scaled by 0.125*log2(e) (exp2-domain softmax); V written TRANSPOSED [bh][d][n].
__global__ __launch_bounds__(256) void rope_kernel(const float* __restrict__ qkv,
                                                   const float* __restrict__ coords,
                                                   float* __restrict__ Qo,
                                                   float* __restrict__ Ko,
                                                   float* __restrict__ Vo)
{
    const int m = blockIdx.x;
    const int b = m >> 11;
    const int n = m & 2047;
    const float c0 = coords[m * 2 + 0];
    const float c1 = coords[m * 2 + 1];
    const float* src = qkv + (size_t)m * (3 * Dd);

    for (int t = threadIdx.x; t < 3 * Dd; t += 256) {
        const int which = t / Dd;
        const int r     = t - which * Dd;
        const int h     = r >> 6;
        const int d     = r & 63;
        float val;
        if (which == 2) {
            val = src[t];
        } else {
            const int slice = d >> 5;
            const int dl    = d & 31;
            const int j     = dl & 15;
            const int isodd = dl >> 4;
            const float coord = slice ? c1 : c0;
            const float invf  = exp2f(-13.0f * (float)j * (1.0f / 16.0f));
            const float f  = coord * invf;
            const float cs = cosf(f);
            const float sn = sinf(f);
            const int   e  = which * Dd + h * 64 + slice * 32 + 2 * j;
            const float t1 = src[e];
            const float t2 = src[e + 1];
            val = isodd ? (t1 * sn + t2 * cs) : (t1 * cs - t2 * sn);
            if (which == 0) val *= 0.18033688011112042f;   // 0.125 * log2(e)
        }
        if (which == 2) {
            Vo[((size_t)(b * Hh + h) * DH + d) * Nn + n] = rnd_tf32(val);
        } else {
            float* dst = (which == 0) ? Qo : Ko;
            dst[((size_t)(b * Hh + h) * Nn + n) * DH + d] = rnd_tf32(val);
        }
    }
}

// ---------------- mma.sync tf32 flash attention ----------------
// Bq=128, Bk=64, 256 threads (8 warps x 16 q-rows). Q in registers.
// P stays in registers: PV uses k-permutation pi(jq)={2jq,2jq+1} so the S
// C-fragment IS the PV A-fragment. No Ps smem at all. 2-stage cp.async KV.
#define KSTR 68
#define VSTR 72
#define KVSTG (64 * KSTR + 64 * VSTR)   /* uint32s per stage */
__global__ __launch_bounds__(256, 2) void attn_mma(const float* __restrict__ Q,
                                                   const float* __restrict__ K,
                                                   const float* __restrict__ VT,
                                                   float* __restrict__ AO)
{
    extern __shared__ __align__(16) uint32_t sa[];   // 2 stages x (K tile | V tile)

    const int tid  = threadIdx.x;
    const int lane = tid & 31;
    const int wid  = tid >> 5;             // 0..7
    const int gq   = lane >> 2;
    const int jq   = lane & 3;
    const int m0   = wid * 16;
    const int bh   = blockIdx.y;
    const int q0   = blockIdx.x * 128;
    const int b    = bh / Hh;
    const int h    = bh - b * Hh;

    const float* Qbh  = Q  + (size_t)bh * Nn * DH;
    const float* Kbh  = K  + (size_t)bh * Nn * DH;
    const float* VTbh = VT + (size_t)bh * DH * Nn;

    // Q A-fragments in registers (loaded once)
    uint4 qa[4][2];
    #pragma unroll
    for (int gh = 0; gh < 4; gh++) {
        const int kc = (gh >> 1) * 32 + (gh & 1) * 4 + jq * 8;
        qa[gh][0] = *(const uint4*)&Qbh[(size_t)(q0 + m0 + gq) * DH + kc];
        qa[gh][1] = *(const uint4*)&Qbh[(size_t)(q0 + m0 + gq + 8) * DH + kc];
    }

    float o[8][4];
    #pragma unroll
    for (int t = 0; t < 8; t++)
        #pragma unroll
        for (int j = 0; j < 4; j++) o[t][j] = 0.f;
    float m_lo = -1e30f, m_hi = -1e30f, l_lo = 0.f, l_hi = 0.f;

#define PREFETCH(IT, S) do {                                                       \
    uint32_t* Kd = sa + (S) * KVSTG;                                               \
    uint32_t* Vd = Kd + 64 * KSTR;                                                 \
    _Pragma("unroll")                                                              \
    for (int p = 0; p < 4; p++) {                                                  \
        const int idx = tid + p * 256;                                             \
        const int row = idx >> 4;                                                  \
        const int c4  = (idx & 15) * 4;                                            \
        cp16(smem_u32(&Kd[row * KSTR + c4]), &Kbh[(size_t)((IT) * 64 + row) * DH + c4]); \
        cp16(smem_u32(&Vd[row * VSTR + c4]), &VTbh[(size_t)row * Nn + (IT) * 64 + c4]);  \
    }                                                                              \
    asm volatile("cp.async.commit_group;" ::: "memory");                           \
} while (0)

    PREFETCH(0, 0);

    const int nT = Nn / 64;
    for (int it = 0; it < nT; it++) {
        const int s = it & 1;
        asm volatile("cp.async.wait_group 0;" ::: "memory");
        __syncthreads();
        if (it + 1 < nT) PREFETCH(it + 1, s ^ 1);

        const uint32_t* Ksm = sa + s * KVSTG;
        const uint32_t* Vsm = Ksm + 64 * KSTR;

        // ---- S = Q K^T ----
        float sc[8][4];
        #pragma unroll
        for (int t = 0; t < 8; t++)
            #pragma unroll
            for (int j = 0; j < 4; j++) sc[t][j] = 0.f;

        #pragma unroll
        for (int gh = 0; gh < 4; gh++) {
            const int kc = (gh >> 1) * 32 + (gh & 1) * 4 + jq * 8;
            const uint4 a0 = qa[gh][0], a1 = qa[gh][1];
            #pragma unroll
            for (int t = 0; t < 8; t++) {
                uint4 bv = *(const uint4*)&Ksm[(t * 8 + gq) * KSTR + kc];
                mma_tf32(sc[t], a0.x, a1.x, a0.y, a1.y, bv.x, bv.y);
                mma_tf32(sc[t], a0.z, a1.z, a0.w, a1.w, bv.z, bv.w);
            }
        }

        // ---- online softmax (log2 domain); rows gq -> c0,c1 ; gq+8 -> c2,c3 ----
        float smax_lo = -1e30f, smax_hi = -1e30f;
        #pragma unroll
        for (int t = 0; t < 8; t++) {
            smax_lo = fmaxf(smax_lo, fmaxf(sc[t][0], sc[t][1]));
            smax_hi = fmaxf(smax_hi, fmaxf(sc[t][2], sc[t][3]));
        }
        #pragma unroll
        for (int off = 1; off <= 2; off <<= 1) {
            smax_lo = fmaxf(smax_lo, __shfl_xor_sync(0xffffffffu, smax_lo, off));
            smax_hi = fmaxf(smax_hi, __shfl_xor_sync(0xffffffffu, smax_hi, off));
        }
        const float mn_lo = fmaxf(m_lo, smax_lo);
        const float mn_hi = fmaxf(m_hi, smax_hi);
        const float cr_lo = exp2f(m_lo - mn_lo);
        const float cr_hi = exp2f(m_hi - mn_hi);
        m_lo = mn_lo; m_hi = mn_hi;

        float ls_lo = 0.f, ls_hi = 0.f;
        #pragma unroll
        for (int t = 0; t < 8; t++) {
            sc[t][0] = exp2f(sc[t][0] - mn_lo);
            sc[t][1] = exp2f(sc[t][1] - mn_lo);
            sc[t][2] = exp2f(sc[t][2] - mn_hi);
            sc[t][3] = exp2f(sc[t][3] - mn_hi);
            ls_lo += sc[t][0] + sc[t][1];
            ls_hi += sc[t][2] + sc[t][3];
        }
        #pragma unroll
        for (int off = 1; off <= 2; off <<= 1) {
            ls_lo += __shfl_xor_sync(0xffffffffu, ls_lo, off);
            ls_hi += __shfl_xor_sync(0xffffffffu, ls_hi, off);
        }
        l_lo = l_lo * cr_lo + ls_lo;
        l_hi = l_hi * cr_hi + ls_hi;
        #pragma unroll
        for (int t = 0; t < 8; t++) {
            o[t][0] *= cr_lo; o[t][1] *= cr_lo;
            o[t][2] *= cr_hi; o[t][3] *= cr_hi;
        }

        // ---- O += P V : P C-frag == A-frag under pi(jq) = {2jq, 2jq+1} ----
        #pragma unroll
        for (int kcb = 0; kcb < 8; kcb++) {
            const uint32_t a0 = cvt_tf32(sc[kcb][0]);   // row gq,   key 8kcb+2jq
            const uint32_t a1 = cvt_tf32(sc[kcb][2]);   // row gq+8, key 8kcb+2jq
            const uint32_t a2 = cvt_tf32(sc[kcb][1]);   // row gq,   key 8kcb+2jq+1
            const uint32_t a3 = cvt_tf32(sc[kcb][3]);   // row gq+8, key 8kcb+2jq+1
            #pragma unroll
            for (int t = 0; t < 8; t++) {
                uint2 bv = *(const uint2*)&Vsm[(t * 8 + gq) * VSTR + kcb * 8 + 2 * jq];
                mma_tf32(o[t], a0, a1, a2, a3, bv.x, bv.y);
            }
        }
    }
#undef PREFETCH

    // epilogue: normalize, round to tf32, write AO[b][n][h*64+d]
    const float inv_lo = 1.0f / l_lo;
    const float inv_hi = 1.0f / l_hi;
    #pragma unroll
    for (int t = 0; t < 8; t++) {
        const int col = h * DH + t * 8 + 2 * jq;
        const size_t r0 = (size_t)(b * Nn + q0 + m0 + gq) * Dd + col;
        const size_t r1 = (size_t)(b * Nn + q0 + m0 + gq + 8) * Dd + col;
        *(float2*)&AO[r0] = make_float2(rnd_tf32(o[t][0] * inv_lo), rnd_tf32(o[t][1] * inv_lo));
        *(float2*)&AO[r1] = make_float2(rnd_tf32(o[t][2] * inv_hi), rnd_tf32(o[t][3] * inv_hi));
    }
}

// ---------------- launch ----------------
extern "C" void kernel_launch(void* const* d_in, const int* in_sizes, int n_in,
                              void* d_out, int out_size)
{
    const float* x      = (const float*)d_in[0];
    const float* coords = (const float*)d_in[1];
    const float* gamma  = (const float*)d_in[2];
    const float* beta   = (const float*)d_in[3];
    const float* wqkv   = (const float*)d_in[4];
    const float* wout   = (const float*)d_in[5];
    float* out = (float*)d_out;

    float *xn, *qkv, *q, *k, *v, *ao, *wq, *wo;
    cudaGetSymbolAddress((void**)&xn,  g_xn);
    cudaGetSymbolAddress((void**)&qkv, g_qkv);
    cudaGetSymbolAddress((void**)&q,   g_q);
    cudaGetSymbolAddress((void**)&k,   g_k);
    cudaGetSymbolAddress((void**)&v,   g_v);
    cudaGetSymbolAddress((void**)&ao,  g_ao);
    cudaGetSymbolAddress((void**)&wq,  g_wq);
    cudaGetSymbolAddress((void**)&wo,  g_wo);

    const int gemm_smem = 3 * 2 * TILE_F * (int)sizeof(float);   // 110592 B
    const int attn_smem = 2 * KVSTG * (int)sizeof(float);        // 71680 B
    cudaFuncSetAttribute(gemm_mma, cudaFuncAttributeMaxDynamicSharedMemorySize, gemm_smem);
    cudaFuncSetAttribute(attn_mma, cudaFuncAttributeMaxDynamicSharedMemorySize, attn_smem);

    const int nwq = 3 * Dd * Dd, nwo = Dd * Dd;
    cvtw_kernel<<<nwq / 1024, 256>>>(wqkv, wq, nwq);
    cvtw_kernel<<<nwo / 1024, 256>>>(wout, wo, nwo);
    ln_kernel<<<M_TOT, 256>>>(x, gamma, beta, xn);
    gemm_mma<<<dim3(3 * Dd / 128, M_TOT / 128), 128, gemm_smem>>>(xn, wq, qkv, 3 * Dd, Dd);
    rope_kernel<<<M_TOT, 256>>>(qkv, coords, q, k, v);
    attn_mma<<<dim3(Nn / 128, BH), 256, attn_smem>>>(q, k, v, ao);
    gemm_mma<<<dim3(Dd / 128, M_TOT / 128), 128, gemm_smem>>>(ao, wo, out, Dd, Dd);
}

// round 10
// speedup vs baseline: 2.2965x; 1.7606x over previous
#include <cuda_runtime.h>
#include <cuda_fp16.h>
#include <math.h>
#include <cstdint>

#define Bb 4
#define Nn 2048
#define Dd 768
#define Hh 12
#define DH 64
#define M_TOT (Bb*Nn)      /* 8192 */
#define BH (Bb*Hh)         /* 48   */

// ---------------- scratch (device globals; no allocs allowed) ----------------
__device__ __half g_xn [(size_t)M_TOT * Dd];
__device__ float  g_qkv[(size_t)M_TOT * 3 * Dd];
__device__ __half g_q  [(size_t)BH * Nn * DH];
__device__ __half g_k  [(size_t)BH * Nn * DH];
__device__ __half g_v  [(size_t)BH * Nn * DH];   // TRANSPOSED: [bh][d][n]
__device__ __half g_ao [(size_t)M_TOT * Dd];
__device__ __half g_wq [(size_t)3 * Dd * Dd];
__device__ __half g_wo [(size_t)Dd * Dd];

// ======================= helpers =======================
__device__ __forceinline__ uint32_t smem_u32(const void* p) {
    uint32_t a;
    asm("{ .reg .u64 t; cvta.to.shared.u64 t, %1; cvt.u32.u64 %0, t; }" : "=r"(a) : "l"(p));
    return a;
}
__device__ __forceinline__ void cp16(uint32_t dst, const void* src) {
    asm volatile("cp.async.cg.shared.global [%0], [%1], 16;" :: "r"(dst), "l"(src) : "memory");
}
__device__ __forceinline__ uint32_t h2(float a, float b) {
    __half2 h = __floats2half2_rn(a, b);
    return *(uint32_t*)&h;
}
__device__ __forceinline__ void mma_f16(float* c, uint32_t a0, uint32_t a1, uint32_t a2, uint32_t a3,
                                        uint32_t b0, uint32_t b1) {
    asm volatile("mma.sync.aligned.m16n8k16.row.col.f32.f16.f16.f32 "
                 "{%0,%1,%2,%3}, {%4,%5,%6,%7}, {%8,%9}, {%0,%1,%2,%3};"
                 : "+f"(c[0]), "+f"(c[1]), "+f"(c[2]), "+f"(c[3])
                 : "r"(a0), "r"(a1), "r"(a2), "r"(a3), "r"(b0), "r"(b1));
}

// ---------------- fp16 conversion pass (weights) ----------------
__global__ __launch_bounds__(256) void cvtw_kernel(const float* __restrict__ src,
                                                   __half* __restrict__ dst, int n)
{
    const int i = (blockIdx.x * 256 + threadIdx.x) * 8;
    if (i < n) {
        float4 v1 = *(const float4*)&src[i];
        float4 v2 = *(const float4*)&src[i + 4];
        uint4 w = make_uint4(h2(v1.x, v1.y), h2(v1.z, v1.w), h2(v2.x, v2.y), h2(v2.z, v2.w));
        *(uint4*)&dst[i] = w;
    }
}

// ---------------- LayerNorm (writes fp16) ----------------
__global__ __launch_bounds__(256) void ln_kernel(const float* __restrict__ x,
                                                 const float* __restrict__ gamma,
                                                 const float* __restrict__ beta,
                                                 __half* __restrict__ xn)
{
    const int row = blockIdx.x;
    const int t   = threadIdx.x;
    const float* xr = x + (size_t)row * Dd;
    float v0 = xr[t], v1 = xr[t + 256], v2 = xr[t + 512];
    float s  = v0 + v1 + v2;
    float sq = v0*v0 + v1*v1 + v2*v2;
    #pragma unroll
    for (int off = 16; off; off >>= 1) {
        s  += __shfl_xor_sync(0xffffffffu, s,  off);
        sq += __shfl_xor_sync(0xffffffffu, sq, off);
    }
    __shared__ float rs[8], rq[8];
    const int w = t >> 5, lane = t & 31;
    if (lane == 0) { rs[w] = s; rq[w] = sq; }
    __syncthreads();
    if (t == 0) {
        float S = 0.f, Q = 0.f;
        #pragma unroll
        for (int i = 0; i < 8; i++) { S += rs[i]; Q += rq[i]; }
        rs[0] = S; rq[0] = Q;
    }
    __syncthreads();
    const float mu   = rs[0] * (1.0f / 768.0f);
    const float var  = rq[0] * (1.0f / 768.0f) - mu * mu;
    const float rstd = rsqrtf(var + 1e-5f);
    __half* xo = xn + (size_t)row * Dd;
    xo[t      ] = __float2half_rn((v0 - mu) * rstd * gamma[t      ] + beta[t      ]);
    xo[t + 256] = __float2half_rn((v1 - mu) * rstd * gamma[t + 256] + beta[t + 256]);
    xo[t + 512] = __float2half_rn((v2 - mu) * rstd * gamma[t + 512] + beta[t + 512]);
}

// ---------------- fp16 m16n8k16 GEMM: C[m,n] = sum_k A[m,k]*W[n,k] ----------------
// 128x128 CTA tile, K chunk 32, 4 warps (64x64 warp tiles), 3-stage cp.async ring.
// k-permutation per k16 block: block0 slots {8jq..8jq+3}, block1 {8jq+4..8jq+7}
// -> one uint4 per row feeds both blocks. Rows 64B, unpadded (conflict-free LDS.128).
#define AS_H 32                 /* halves per smem row */
#define TILE_H (128 * AS_H)     /* halves per tile (8 KB) */
__global__ __launch_bounds__(128, 2) void gemm_mma(const __half* __restrict__ A,
                                                   const __half* __restrict__ W,
                                                   float* __restrict__ C,
                                                   int Np, int K)
{
    extern __shared__ __align__(16) __half sh[];
    const int tid  = threadIdx.x;
    const int lane = tid & 31;
    const int wid  = tid >> 5;
    const int wm   = wid >> 1;
    const int wn   = wid & 1;
    const int gq   = lane >> 2;
    const int jq   = lane & 3;
    const int bm   = blockIdx.y * 128;
    const int bn   = blockIdx.x * 128;

    float acc[4][8][4];
    #pragma unroll
    for (int i = 0; i < 4; i++)
        #pragma unroll
        for (int j = 0; j < 8; j++)
            #pragma unroll
            for (int q = 0; q < 4; q++) acc[i][j][q] = 0.f;

    const int nCh = K / 32;

#define LOAD_STAGE(IT, S) do {                                                  \
    const __half* Ab = A + (size_t)bm * K + (IT) * 32;                          \
    const __half* Wb = W + (size_t)bn * K + (IT) * 32;                          \
    __half* As_ = sh + (S) * (2 * TILE_H);                                      \
    __half* Bs_ = As_ + TILE_H;                                                 \
    _Pragma("unroll")                                                           \
    for (int p = 0; p < 4; p++) {                                               \
        const int idx = tid + p * 128;                                          \
        const int row = idx >> 2;                                               \
        const int c8  = (idx & 3) * 8;                                          \
        cp16(smem_u32(&As_[row * AS_H + c8]), &Ab[(size_t)row * K + c8]);       \
        cp16(smem_u32(&Bs_[row * AS_H + c8]), &Wb[(size_t)row * K + c8]);       \
    }                                                                           \
    asm volatile("cp.async.commit_group;" ::: "memory");                        \
} while (0)

    LOAD_STAGE(0, 0);
    LOAD_STAGE(1, 1);

    int s = 0, s2 = 2;
    for (int it = 0; it < nCh; it++) {
        if (it + 1 < nCh) {
            asm volatile("cp.async.wait_group 1;" ::: "memory");
        } else {
            asm volatile("cp.async.wait_group 0;" ::: "memory");
        }
        __syncthreads();
        if (it + 2 < nCh) LOAD_STAGE(it + 2, s2);

        const __half* As_ = sh + s * (2 * TILE_H);
        const __half* Bs_ = As_ + TILE_H;

        uint4 afr[8];
        #pragma unroll
        for (int mf = 0; mf < 4; mf++) {
            const int m = wm * 64 + mf * 16 + gq;
            afr[2 * mf]     = *(const uint4*)&As_[m * AS_H + 8 * jq];
            afr[2 * mf + 1] = *(const uint4*)&As_[(m + 8) * AS_H + 8 * jq];
        }
        #pragma unroll
        for (int ng = 0; ng < 2; ng++) {
            uint4 bfr[4];
            #pragma unroll
            for (int j = 0; j < 4; j++) {
                const int n = wn * 64 + (ng * 4 + j) * 8 + gq;
                bfr[j] = *(const uint4*)&Bs_[n * AS_H + 8 * jq];
            }
            #pragma unroll
            for (int mf = 0; mf < 4; mf++) {
                #pragma unroll
                for (int j = 0; j < 4; j++) {
                    float* a = acc[mf][ng * 4 + j];
                    mma_f16(a, afr[2*mf].x, afr[2*mf+1].x, afr[2*mf].y, afr[2*mf+1].y,
                            bfr[j].x, bfr[j].y);
                    mma_f16(a, afr[2*mf].z, afr[2*mf+1].z, afr[2*mf].w, afr[2*mf+1].w,
                            bfr[j].z, bfr[j].w);
                }
            }
        }
        s  = (s  == 2) ? 0 : s + 1;
        s2 = (s2 == 2) ? 0 : s2 + 1;
    }

    #pragma unroll
    for (int mf = 0; mf < 4; mf++) {
        const int r = bm + wm * 64 + mf * 16 + gq;
        #pragma unroll
        for (int nf = 0; nf < 8; nf++) {
            const int n0 = bn + wn * 64 + nf * 8 + 2 * jq;
            *(float2*)&C[(size_t)r * Np + n0]       = make_float2(acc[mf][nf][0], acc[mf][nf][1]);
            *(float2*)&C[(size_t)(r + 8) * Np + n0] = make_float2(acc[mf][nf][2], acc[mf][nf][3]);
        }
    }
#undef LOAD_STAGE
}

// ---------------- RoPE + head split (fp16 out) ----------------
// Q scaled by 0.125*log2(e); V written TRANSPOSED [bh][d][n].
__global__ __launch_bounds__(256) void rope_kernel(const float* __restrict__ qkv,
                                                   const float* __restrict__ coords,
                                                   __half* __restrict__ Qo,
                                                   __half* __restrict__ Ko,
                                                   __half* __restrict__ Vo)
{
    const int m = blockIdx.x;
    const int b = m >> 11;
    const int n = m & 2047;
    const float c0 = coords[m * 2 + 0];
    const float c1 = coords[m * 2 + 1];
    const float* src = qkv + (size_t)m * (3 * Dd);

    for (int t = threadIdx.x; t < 3 * Dd; t += 256) {
        const int which = t / Dd;
        const int r     = t - which * Dd;
        const int h     = r >> 6;
        const int d     = r & 63;
        float val;
        if (which == 2) {
            val = src[t];
        } else {
            const int slice = d >> 5;
            const int dl    = d & 31;
            const int j     = dl & 15;
            const int isodd = dl >> 4;
            const float coord = slice ? c1 : c0;
            const float invf  = exp2f(-13.0f * (float)j * (1.0f / 16.0f));
            const float f  = coord * invf;
            const float cs = cosf(f);
            const float sn = sinf(f);
            const int   e  = which * Dd + h * 64 + slice * 32 + 2 * j;
            const float t1 = src[e];
            const float t2 = src[e + 1];
            val = isodd ? (t1 * sn + t2 * cs) : (t1 * cs - t2 * sn);
            if (which == 0) val *= 0.18033688011112042f;   // 0.125 * log2(e)
        }
        if (which == 2) {
            Vo[((size_t)(b * Hh + h) * DH + d) * Nn + n] = __float2half_rn(val);
        } else {
            __half* dst = (which == 0) ? Qo : Ko;
            dst[((size_t)(b * Hh + h) * Nn + n) * DH + d] = __float2half_rn(val);
        }
    }
}

// ---------------- fp16 m16n8k16 flash attention ----------------
// Bq=128, Bk=64, 256 threads (8 warps x 16 q-rows). Q in registers, P in registers.
// K tile rows padded to 96 halves (192B, conflict-free LDS.128);
// V tile rows padded to 72 halves (144B, conflict-free LDS.32).
#define KSTRH 96
#define VSTRH 72
#define KVSTG_H (64 * KSTRH + 64 * VSTRH)   /* halves per stage */
__global__ __launch_bounds__(256, 2) void attn_mma(const __half* __restrict__ Q,
                                                   const __half* __restrict__ K,
                                                   const __half* __restrict__ VT,
                                                   __half* __restrict__ AO)
{
    extern __shared__ __align__(16) __half sa[];   // 2 stages x (K tile | V tile)

    const int tid  = threadIdx.x;
    const int lane = tid & 31;
    const int wid  = tid >> 5;             // 0..7
    const int gq   = lane >> 2;
    const int jq   = lane & 3;
    const int m0   = wid * 16;
    const int bh   = blockIdx.y;
    const int q0   = blockIdx.x * 128;
    const int b    = bh / Hh;
    const int h    = bh - b * Hh;

    const __half* Qbh  = Q  + (size_t)bh * Nn * DH;
    const __half* Kbh  = K  + (size_t)bh * Nn * DH;
    const __half* VTbh = VT + (size_t)bh * DH * Nn;

    // Q A-fragments (loaded once): chunk c covers d in [32c, 32c+32)
    uint4 qa[2][2];
    #pragma unroll
    for (int c = 0; c < 2; c++) {
        qa[c][0] = *(const uint4*)&Qbh[(size_t)(q0 + m0 + gq) * DH + c * 32 + 8 * jq];
        qa[c][1] = *(const uint4*)&Qbh[(size_t)(q0 + m0 + gq + 8) * DH + c * 32 + 8 * jq];
    }

    float o[8][4];
    #pragma unroll
    for (int t = 0; t < 8; t++)
        #pragma unroll
        for (int j = 0; j < 4; j++) o[t][j] = 0.f;
    float m_lo = -1e30f, m_hi = -1e30f, l_lo = 0.f, l_hi = 0.f;

#define PREFETCH(IT, S) do {                                                        \
    __half* Kd = sa + (S) * KVSTG_H;                                                \
    __half* Vd = Kd + 64 * KSTRH;                                                   \
    _Pragma("unroll")                                                               \
    for (int p = 0; p < 2; p++) {                                                   \
        const int idx = tid + p * 256;                                              \
        const int row = idx >> 3;                                                   \
        const int c8  = (idx & 7) * 8;                                              \
        cp16(smem_u32(&Kd[row * KSTRH + c8]), &Kbh[(size_t)((IT) * 64 + row) * DH + c8]); \
        cp16(smem_u32(&Vd[row * VSTRH + c8]), &VTbh[(size_t)row * Nn + (IT) * 64 + c8]);  \
    }                                                                               \
    asm volatile("cp.async.commit_group;" ::: "memory");                            \
} while (0)

    PREFETCH(0, 0);

    const int nT = Nn / 64;
    for (int it = 0; it < nT; it++) {
        const int s = it & 1;
        asm volatile("cp.async.wait_group 0;" ::: "memory");
        __syncthreads();
        if (it + 1 < nT) PREFETCH(it + 1, s ^ 1);

        const __half* Ksm = sa + s * KVSTG_H;
        const __half* Vsm = Ksm + 64 * KSTRH;

        // ---- S = Q K^T ----
        float sc[8][4];
        #pragma unroll
        for (int t = 0; t < 8; t++)
            #pragma unroll
            for (int j = 0; j < 4; j++) sc[t][j] = 0.f;

        #pragma unroll
        for (int c = 0; c < 2; c++) {
            const uint4 a0 = qa[c][0], a1 = qa[c][1];
            #pragma unroll
            for (int t = 0; t < 8; t++) {
                uint4 kv = *(const uint4*)&Ksm[(t * 8 + gq) * KSTRH + c * 32 + 8 * jq];
                mma_f16(sc[t], a0.x, a1.x, a0.y, a1.y, kv.x, kv.y);
                mma_f16(sc[t], a0.z, a1.z, a0.w, a1.w, kv.z, kv.w);
            }
        }

        // ---- online softmax (log2 domain); rows gq -> c0,c1 ; gq+8 -> c2,c3 ----
        float smax_lo = -1e30f, smax_hi = -1e30f;
        #pragma unroll
        for (int t = 0; t < 8; t++) {
            smax_lo = fmaxf(smax_lo, fmaxf(sc[t][0], sc[t][1]));
            smax_hi = fmaxf(smax_hi, fmaxf(sc[t][2], sc[t][3]));
        }
        #pragma unroll
        for (int off = 1; off <= 2; off <<= 1) {
            smax_lo = fmaxf(smax_lo, __shfl_xor_sync(0xffffffffu, smax_lo, off));
            smax_hi = fmaxf(smax_hi, __shfl_xor_sync(0xffffffffu, smax_hi, off));
        }
        const float mn_lo = fmaxf(m_lo, smax_lo);
        const float mn_hi = fmaxf(m_hi, smax_hi);
        const float cr_lo = exp2f(m_lo - mn_lo);
        const float cr_hi = exp2f(m_hi - mn_hi);
        m_lo = mn_lo; m_hi = mn_hi;

        float ls_lo = 0.f, ls_hi = 0.f;
        #pragma unroll
        for (int t = 0; t < 8; t++) {
            sc[t][0] = exp2f(sc[t][0] - mn_lo);
            sc[t][1] = exp2f(sc[t][1] - mn_lo);
            sc[t][2] = exp2f(sc[t][2] - mn_hi);
            sc[t][3] = exp2f(sc[t][3] - mn_hi);
            ls_lo += sc[t][0] + sc[t][1];
            ls_hi += sc[t][2] + sc[t][3];
        }
        #pragma unroll
        for (int off = 1; off <= 2; off <<= 1) {
            ls_lo += __shfl_xor_sync(0xffffffffu, ls_lo, off);
            ls_hi += __shfl_xor_sync(0xffffffffu, ls_hi, off);
        }
        l_lo = l_lo * cr_lo + ls_lo;
        l_hi = l_hi * cr_hi + ls_hi;
        #pragma unroll
        for (int t = 0; t < 8; t++) {
            o[t][0] *= cr_lo; o[t][1] *= cr_lo;
            o[t][2] *= cr_hi; o[t][3] *= cr_hi;
        }

        // ---- O += P V : P C-frags pack directly into fp16 A-frags ----
        // key-block c = keys [16c,16c+16) = S n-blocks (2c, 2c+1)
        #pragma unroll
        for (int c = 0; c < 4; c++) {
            const uint32_t a0 = h2(sc[2*c][0],     sc[2*c][1]);      // row gq,   keys 16c+2jq,+1
            const uint32_t a1 = h2(sc[2*c][2],     sc[2*c][3]);      // row gq+8
            const uint32_t a2 = h2(sc[2*c + 1][0], sc[2*c + 1][1]);  // row gq,   keys 16c+8+2jq,+1
            const uint32_t a3 = h2(sc[2*c + 1][2], sc[2*c + 1][3]);  // row gq+8
            #pragma unroll
            for (int t = 0; t < 8; t++) {
                const uint32_t b0 = *(const uint32_t*)&Vsm[(t * 8 + gq) * VSTRH + c * 16 + 2 * jq];
                const uint32_t b1 = *(const uint32_t*)&Vsm[(t * 8 + gq) * VSTRH + c * 16 + 8 + 2 * jq];
                mma_f16(o[t], a0, a1, a2, a3, b0, b1);
            }
        }
    }
#undef PREFETCH

    // epilogue: normalize, write fp16 AO[b][n][h*64+d]
    const float inv_lo = 1.0f / l_lo;
    const float inv_hi = 1.0f / l_hi;
    #pragma unroll
    for (int t = 0; t < 8; t++) {
        const int col = h * DH + t * 8 + 2 * jq;
        const size_t r0 = (size_t)(b * Nn + q0 + m0 + gq) * Dd + col;
        const size_t r1 = (size_t)(b * Nn + q0 + m0 + gq + 8) * Dd + col;
        *(uint32_t*)&AO[r0] = h2(o[t][0] * inv_lo, o[t][1] * inv_lo);
        *(uint32_t*)&AO[r1] = h2(o[t][2] * inv_hi, o[t][3] * inv_hi);
    }
}

// ---------------- launch ----------------
extern "C" void kernel_launch(void* const* d_in, const int* in_sizes, int n_in,
                              void* d_out, int out_size)
{
    const float* x      = (const float*)d_in[0];
    const float* coords = (const float*)d_in[1];
    const float* gamma  = (const float*)d_in[2];
    const float* beta   = (const float*)d_in[3];
    const float* wqkv   = (const float*)d_in[4];
    const float* wout   = (const float*)d_in[5];
    float* out = (float*)d_out;

    __half *xn, *q, *k, *v, *ao, *wq, *wo;
    float *qkv;
    cudaGetSymbolAddress((void**)&xn,  g_xn);
    cudaGetSymbolAddress((void**)&qkv, g_qkv);
    cudaGetSymbolAddress((void**)&q,   g_q);
    cudaGetSymbolAddress((void**)&k,   g_k);
    cudaGetSymbolAddress((void**)&v,   g_v);
    cudaGetSymbolAddress((void**)&ao,  g_ao);
    cudaGetSymbolAddress((void**)&wq,  g_wq);
    cudaGetSymbolAddress((void**)&wo,  g_wo);

    const int gemm_smem = 3 * 2 * TILE_H * (int)sizeof(__half);   // 49152 B
    const int attn_smem = 2 * KVSTG_H * (int)sizeof(__half);      // 43008 B
    cudaFuncSetAttribute(gemm_mma, cudaFuncAttributeMaxDynamicSharedMemorySize, gemm_smem);
    cudaFuncSetAttribute(attn_mma, cudaFuncAttributeMaxDynamicSharedMemorySize, attn_smem);

    const int nwq = 3 * Dd * Dd, nwo = Dd * Dd;
    cvtw_kernel<<<nwq / 2048, 256>>>(wqkv, wq, nwq);
    cvtw_kernel<<<nwo / 2048, 256>>>(wout, wo, nwo);
    ln_kernel<<<M_TOT, 256>>>(x, gamma, beta, xn);
    gemm_mma<<<dim3(3 * Dd / 128, M_TOT / 128), 128, gemm_smem>>>(xn, wq, qkv, 3 * Dd, Dd);
    rope_kernel<<<M_TOT, 256>>>(qkv, coords, q, k, v);
    attn_mma<<<dim3(Nn / 128, BH), 256, attn_smem>>>(q, k, v, ao);
    gemm_mma<<<dim3(Dd / 128, M_TOT / 128), 128, gemm_smem>>>(ao, wo, out, Dd, Dd);
}